// round 5
// baseline (speedup 1.0000x reference)
#include <cuda_runtime.h>
#include <math.h>

#define BSZ    2
#define LSEQ   2048
#define DMODEL 1024
#define INNER  2048
#define MROWS  4096      // BSZ*LSEQ
#define NIN    4096      // 2*INNER
#define DTR    64
#define DST    16
#define XD     96        // DTR + 2*DST

// ---- scratch (device globals; no allocation allowed) ----
__device__ float g_xr[(size_t)MROWS * NIN];     // x @ W_in^T  (xs | res)
__device__ float g_xs[(size_t)MROWS * INNER];   // conv+silu output
__device__ float g_xdbl[(size_t)MROWS * XD];    // xs @ W_x^T
__device__ float g_dt[(size_t)MROWS * INNER];   // dt2 = softplus(softplus(.))
__device__ float g_y[(size_t)MROWS * INNER];    // scan output (fused epilogue)

__device__ __forceinline__ float softplusf(float x) {
    return fmaxf(x, 0.f) + log1pf(__expf(-fabsf(x)));
}

// ============================================================
// C[M,N] = A[M,K] * B[N,K]^T   (both K-contiguous), 128x128x8 tiles
// ============================================================
__global__ __launch_bounds__(256, 2) void sgemm_nt(
    const float* __restrict__ A, const float* __restrict__ B,
    float* __restrict__ C, int M, int N, int K)
{
    __shared__ float As[8][128];
    __shared__ float Bs[8][128];
    const int tid = threadIdx.x;
    const int bm = blockIdx.y * 128;
    const int bn = blockIdx.x * 128;
    const int tx = tid & 15;
    const int ty = tid >> 4;
    const int lRow = tid >> 1;
    const int lK = (tid & 1) << 2;
    const float* Ap = A + (size_t)(bm + lRow) * K + lK;
    const float* Bp = B + (size_t)(bn + lRow) * K + lK;

    float acc[8][8];
#pragma unroll
    for (int i = 0; i < 8; i++)
#pragma unroll
        for (int j = 0; j < 8; j++) acc[i][j] = 0.f;

    for (int k0 = 0; k0 < K; k0 += 8) {
        float4 av = *(const float4*)(Ap + k0);
        float4 bv = *(const float4*)(Bp + k0);
        As[lK + 0][lRow] = av.x; As[lK + 1][lRow] = av.y;
        As[lK + 2][lRow] = av.z; As[lK + 3][lRow] = av.w;
        Bs[lK + 0][lRow] = bv.x; Bs[lK + 1][lRow] = bv.y;
        Bs[lK + 2][lRow] = bv.z; Bs[lK + 3][lRow] = bv.w;
        __syncthreads();
#pragma unroll
        for (int k = 0; k < 8; k++) {
            float4 a0 = *(const float4*)&As[k][ty * 8];
            float4 a1 = *(const float4*)&As[k][ty * 8 + 4];
            float4 b0 = *(const float4*)&Bs[k][tx * 8];
            float4 b1 = *(const float4*)&Bs[k][tx * 8 + 4];
            float ar[8] = {a0.x, a0.y, a0.z, a0.w, a1.x, a1.y, a1.z, a1.w};
            float br[8] = {b0.x, b0.y, b0.z, b0.w, b1.x, b1.y, b1.z, b1.w};
#pragma unroll
            for (int i = 0; i < 8; i++)
#pragma unroll
                for (int j = 0; j < 8; j++)
                    acc[i][j] = fmaf(ar[i], br[j], acc[i][j]);
        }
        __syncthreads();
    }
#pragma unroll
    for (int i = 0; i < 8; i++) {
        float* Cp = C + (size_t)(bm + ty * 8 + i) * N + bn + tx * 8;
        float4 c0 = {acc[i][0], acc[i][1], acc[i][2], acc[i][3]};
        float4 c1 = {acc[i][4], acc[i][5], acc[i][6], acc[i][7]};
        *(float4*)Cp = c0;
        *(float4*)(Cp + 4) = c1;
    }
}

// ============================================================
// Depthwise causal conv (width 4) + bias + silu over xs half of g_xr
// out[t] = w0*in[t-3] + w1*in[t-2] + w2*in[t-1] + w3*in[t] + b
// ============================================================
__global__ void conv_silu_kernel(const float* __restrict__ conv_w,
                                 const float* __restrict__ conv_b)
{
    int idx = blockIdx.x * blockDim.x + threadIdx.x;
    if (idx >= MROWS * INNER) return;
    int c = idx & (INNER - 1);
    int m = idx >> 11;           // / INNER
    int l = m & (LSEQ - 1);
    float w0 = conv_w[c * 4 + 0], w1 = conv_w[c * 4 + 1];
    float w2 = conv_w[c * 4 + 2], w3 = conv_w[c * 4 + 3];
    float s = conv_b[c];
    s = fmaf(w3, g_xr[(size_t)m * NIN + c], s);
    if (l >= 1) s = fmaf(w2, g_xr[(size_t)(m - 1) * NIN + c], s);
    if (l >= 2) s = fmaf(w1, g_xr[(size_t)(m - 2) * NIN + c], s);
    if (l >= 3) s = fmaf(w0, g_xr[(size_t)(m - 3) * NIN + c], s);
    float sig = 1.f / (1.f + __expf(-s));
    g_xs[idx] = s * sig;
}

// ============================================================
// x_dbl[M,96] = g_xs[M,2048] @ W_x[96,2048]^T
// block: 16 rows, blockDim (96,4)
// ============================================================
__global__ void xdbl_kernel(const float* __restrict__ W_x)
{
    __shared__ float xsh[16][128];
    int j = threadIdx.x;          // 0..95 (output col)
    int y = threadIdx.y;          // 0..3
    int rb = blockIdx.x * 16;
    float acc[4] = {0.f, 0.f, 0.f, 0.f};
    int t = y * 96 + j;           // 0..383
    for (int k0 = 0; k0 < INNER; k0 += 128) {
        for (int e = t; e < 16 * 128; e += 384) {
            int rr = e >> 7, kk = e & 127;
            xsh[rr][kk] = g_xs[(size_t)(rb + rr) * INNER + k0 + kk];
        }
        __syncthreads();
        const float* wrow = W_x + (size_t)j * INNER + k0;
#pragma unroll 4
        for (int kk = 0; kk < 128; kk++) {
            float w = wrow[kk];
            acc[0] = fmaf(xsh[y + 0][kk], w, acc[0]);
            acc[1] = fmaf(xsh[y + 4][kk], w, acc[1]);
            acc[2] = fmaf(xsh[y + 8][kk], w, acc[2]);
            acc[3] = fmaf(xsh[y + 12][kk], w, acc[3]);
        }
        __syncthreads();
    }
#pragma unroll
    for (int i = 0; i < 4; i++)
        g_xdbl[(size_t)(rb + y + 4 * i) * XD + j] = acc[i];
}

// ============================================================
// dt2 = softplus(softplus(x_dbl[:, :64] @ W_dt^T + b_dt)); 64x64 tiles, K=64
// ============================================================
__global__ __launch_bounds__(256) void dt_kernel(const float* __restrict__ W_dt,
                                                 const float* __restrict__ b_dt)
{
    __shared__ float Xs[64][65];
    __shared__ float Ws[64][65];
    int tid = threadIdx.x;
    int rb = blockIdx.y * 64, cb = blockIdx.x * 64;
    for (int e = tid; e < 64 * 64; e += 256) {
        int r = e >> 6, k = e & 63;
        Xs[r][k] = g_xdbl[(size_t)(rb + r) * XD + k];
        Ws[r][k] = W_dt[(size_t)(cb + r) * DTR + k];
    }
    __syncthreads();
    int tx = tid & 15, ty = tid >> 4;
    float acc[4][4];
#pragma unroll
    for (int i = 0; i < 4; i++)
#pragma unroll
        for (int j = 0; j < 4; j++) acc[i][j] = 0.f;
#pragma unroll 8
    for (int k = 0; k < 64; k++) {
        float a[4], b[4];
#pragma unroll
        for (int i = 0; i < 4; i++) { a[i] = Xs[ty * 4 + i][k]; b[i] = Ws[tx * 4 + i][k]; }
#pragma unroll
        for (int i = 0; i < 4; i++)
#pragma unroll
            for (int j = 0; j < 4; j++)
                acc[i][j] = fmaf(a[i], b[j], acc[i][j]);
    }
#pragma unroll
    for (int i = 0; i < 4; i++)
#pragma unroll
        for (int j = 0; j < 4; j++) {
            int r = rb + ty * 4 + i, d = cb + tx * 4 + j;
            float v = acc[i][j] + b_dt[d];
            v = softplusf(v);      // dt
            v = softplusf(v);      // dt2 (reference double-softplus)
            g_dt[(size_t)r * INNER + d] = v;
        }
}

// ============================================================
// Selective scan. One 16-lane group per channel (2 channels / warp).
// h[n] per lane; y = reduce_n(h*C); fused: (y + xs*D) * silu(res)
// ============================================================
__global__ __launch_bounds__(256) void scan_kernel(const float* __restrict__ A_log,
                                                   const float* __restrict__ D_par)
{
    int w = blockIdx.x * 8 + (threadIdx.x >> 5);   // global warp 0..2047
    int lane = threadIdx.x & 31;
    int b = w >> 10;                               // batch
    int pair = w & 1023;
    int d = pair * 2 + ((lane >> 4) & 1);          // channel
    int n = lane & 15;                             // state index

    float a = -__expf(A_log[d * DST + n]);
    float Dv = D_par[d];
    float h = 0.f;

    size_t base = (size_t)b * LSEQ;
    for (int t = 0; t < LSEQ; t++) {
        size_t m = base + t;
        float dt = g_dt[m * INNER + d];
        float xv = g_xs[m * INNER + d];
        float Bn = g_xdbl[m * XD + DTR + n];
        float Cn = g_xdbl[m * XD + DTR + DST + n];
        float dA = __expf(dt * a);
        h = fmaf(dA, h, dt * Bn * xv);
        float pv = h * Cn;
        pv += __shfl_xor_sync(0xffffffffu, pv, 8);
        pv += __shfl_xor_sync(0xffffffffu, pv, 4);
        pv += __shfl_xor_sync(0xffffffffu, pv, 2);
        pv += __shfl_xor_sync(0xffffffffu, pv, 1);
        if (n == 0) {
            float resv = g_xr[m * NIN + INNER + d];
            float silu_r = resv / (1.f + __expf(-resv));
            g_y[m * INNER + d] = (pv + xv * Dv) * silu_r;
        }
    }
}

// ============================================================
extern "C" void kernel_launch(void* const* d_in, const int* in_sizes, int n_in,
                              void* d_out, int out_size)
{
    const float* x      = (const float*)d_in[0];
    const float* W_in   = (const float*)d_in[1];
    const float* conv_w = (const float*)d_in[2];
    const float* conv_b = (const float*)d_in[3];
    const float* W_x    = (const float*)d_in[4];
    const float* W_dt   = (const float*)d_in[5];
    const float* b_dt   = (const float*)d_in[6];
    const float* A_log  = (const float*)d_in[7];
    const float* D_par  = (const float*)d_in[8];
    const float* W_out  = (const float*)d_in[9];
    float* out = (float*)d_out;

    float *xr_p, *y_p;
    cudaGetSymbolAddress((void**)&xr_p, g_xr);
    cudaGetSymbolAddress((void**)&y_p,  g_y);

    // 1) xr = x @ W_in^T   [4096,4096] = [4096,1024] x [4096,1024]^T
    sgemm_nt<<<dim3(NIN / 128, MROWS / 128), 256>>>(x, W_in, xr_p, MROWS, NIN, DMODEL);

    // 2) depthwise causal conv + silu -> g_xs
    conv_silu_kernel<<<(MROWS * INNER + 255) / 256, 256>>>(conv_w, conv_b);

    // 3) x_dbl = xs @ W_x^T  [4096,96]
    xdbl_kernel<<<MROWS / 16, dim3(96, 4)>>>(W_x);

    // 4) dt2 = softplus(softplus(x_dbl[:,:64] @ W_dt^T + b_dt))
    dt_kernel<<<dim3(INNER / 64, MROWS / 64), 256>>>(W_dt, b_dt);

    // 5) selective scan + fused epilogue -> g_y
    scan_kernel<<<256, 256>>>(A_log, D_par);

    // 6) out = y @ W_out^T  [4096,1024]
    sgemm_nt<<<dim3(DMODEL / 128, MROWS / 128), 256>>>(y_p, W_out, out, MROWS, DMODEL, INNER);
}

// round 9
// speedup vs baseline: 1.2803x; 1.2803x over previous
#include <cuda_runtime.h>
#include <cuda_bf16.h>
#include <math.h>
#include <stdint.h>

#define BSZ    2
#define LSEQ   2048
#define DMODEL 1024
#define INNER  2048
#define MROWS  4096      // BSZ*LSEQ
#define NIN    4096      // 2*INNER
#define DTR    64
#define DST    16
#define XD     96        // DTR + 2*DST

// tcgen05 PTX is only legal in the arch-specific target pass (sm_103a /
// compute_103a). The harness also emits a plain compute_103 PTX pass; give
// that pass an empty kernel body so ptxas doesn't abort. At runtime the
// sm_103a cubin is selected, so the guarded path is what executes.
#if defined(__CUDA_ARCH_FEAT_SM103_ALL) || defined(__CUDA_ARCH_FEAT_SM100_ALL)
#define TC_OK 1
#else
#define TC_OK 0
#endif

// ---- scratch (device globals; no allocation allowed) ----
__device__ float g_xr[(size_t)MROWS * NIN];     // x @ W_in^T  (xs | res)
__device__ float g_xs[(size_t)MROWS * INNER];   // conv+silu output
__device__ float g_xdbl[(size_t)MROWS * XD];    // xs @ W_x^T
__device__ float g_dt[(size_t)MROWS * INNER];   // dt2
__device__ float g_y[(size_t)MROWS * INNER];    // scan output

__device__ __forceinline__ float softplusf(float x) {
    return fmaxf(x, 0.f) + __logf(1.f + __expf(-fabsf(x)));
}

// ============================================================
// tcgen05 bf16 split-GEMM:  C[M,N] = A[M,K] * B[N,K]^T  (fp32 in/out)
// Tile 128x128, K-chunks of 64 bf16 (128B rows, SW128), SS mode, cg1.
// 3-term bf16 split for fp32-level accuracy.
// ============================================================
#define TC_BM 128
#define TC_BN 128
#define TC_BK 64
#define TC_TILE_BYTES 16384                 // 128 rows * 128 bytes
#define TC_SMEM_BYTES (1024 + 4 * TC_TILE_BYTES)   // 66560
#define TC_IDESC 0x8200490u                 // F32 acc, BF16xBF16, M=128, N=128

__device__ __forceinline__ uint32_t smem_u32(const void* p) {
    uint32_t a;
    asm("{ .reg .u64 t; cvta.to.shared.u64 t, %1; cvt.u32.u64 %0, t; }"
        : "=r"(a) : "l"(p));
    return a;
}

#if TC_OK
__device__ __forceinline__ uint64_t make_sw128_desc(uint32_t addr) {
    // layout SW128 (2<<61) | version 1 (1<<46) | SBO=64 | LBO=1
    return ( (uint64_t)2 << 61 ) | ( (uint64_t)1 << 46 )
         | ( (uint64_t)64 << 32 ) | ( (uint64_t)1 << 16 )
         | ( (uint64_t)(addr >> 4) & 0x3FFF );
}

__device__ __forceinline__ void mma_ss_bf16(uint32_t d, uint64_t ad, uint64_t bd,
                                            uint32_t acc) {
    asm volatile(
        "{\n\t.reg .pred p;\n\t"
        "setp.ne.u32 p, %4, 0;\n\t"
        "tcgen05.mma.cta_group::1.kind::f16 [%0], %1, %2, %3, {%5, %5, %5, %5}, p;\n\t}"
        :: "r"(d), "l"(ad), "l"(bd), "r"(TC_IDESC), "r"(acc), "r"(0u)
        : "memory");
}

__device__ __forceinline__ void mbar_wait_parity(uint32_t mbar, uint32_t parity) {
    asm volatile(
        "{\n\t.reg .pred P;\n\t"
        "WL_%=:\n\t"
        "mbarrier.try_wait.parity.acquire.cta.shared::cta.b64 P, [%0], %1, 0x989680;\n\t"
        "@!P bra WL_%=;\n\t}"
        :: "r"(mbar), "r"(parity) : "memory");
}

__device__ __forceinline__ void tmem_ld32(uint32_t* r, uint32_t addr) {
    asm volatile(
        "tcgen05.ld.sync.aligned.32x32b.x32.b32 "
        "{%0, %1, %2, %3, %4, %5, %6, %7, "
        " %8, %9, %10, %11, %12, %13, %14, %15, "
        " %16, %17, %18, %19, %20, %21, %22, %23, "
        " %24, %25, %26, %27, %28, %29, %30, %31}, [%32];"
        : "=r"(r[0]), "=r"(r[1]), "=r"(r[2]), "=r"(r[3]),
          "=r"(r[4]), "=r"(r[5]), "=r"(r[6]), "=r"(r[7]),
          "=r"(r[8]), "=r"(r[9]), "=r"(r[10]), "=r"(r[11]),
          "=r"(r[12]), "=r"(r[13]), "=r"(r[14]), "=r"(r[15]),
          "=r"(r[16]), "=r"(r[17]), "=r"(r[18]), "=r"(r[19]),
          "=r"(r[20]), "=r"(r[21]), "=r"(r[22]), "=r"(r[23]),
          "=r"(r[24]), "=r"(r[25]), "=r"(r[26]), "=r"(r[27]),
          "=r"(r[28]), "=r"(r[29]), "=r"(r[30]), "=r"(r[31])
        : "r"(addr));
}
#endif // TC_OK

__global__ __launch_bounds__(256) void tc_gemm_nt(
    const float* __restrict__ A, const float* __restrict__ B,
    float* __restrict__ C, int M, int N, int K)
{
#if TC_OK
    extern __shared__ char smem[];
    const uint32_t sb = smem_u32(smem);
    const uint32_t MBAR = sb + 8;
    const uint32_t S_AH = sb + 1024;
    const uint32_t S_AL = S_AH + TC_TILE_BYTES;
    const uint32_t S_BH = S_AL + TC_TILE_BYTES;
    const uint32_t S_BL = S_BH + TC_TILE_BYTES;
    char* p_ah = smem + 1024;
    char* p_al = p_ah + TC_TILE_BYTES;
    char* p_bh = p_al + TC_TILE_BYTES;
    char* p_bl = p_bh + TC_TILE_BYTES;

    const int tid = threadIdx.x;
    const int wid = tid >> 5, lid = tid & 31;
    const int bm = blockIdx.y * TC_BM;
    const int bn = blockIdx.x * TC_BN;

    // TMEM alloc (warp 0) + mbarrier init
    if (wid == 0) {
        asm volatile(
            "tcgen05.alloc.cta_group::1.sync.aligned.shared::cta.b32 [%0], %1;"
            :: "r"(sb), "r"(128u) : "memory");
    }
    if (tid == 0) {
        asm volatile("mbarrier.init.shared.b64 [%0], 1;" :: "r"(MBAR) : "memory");
    }
    __syncthreads();
    uint32_t tmem;
    asm volatile("ld.shared.b32 %0, [%1];" : "=r"(tmem) : "r"(sb));

    const int r0 = tid >> 4;   // 0..15
    const int c4 = tid & 15;   // float4 index within 64-float chunk row
    const int nchunks = K / TC_BK;

    for (int ch = 0; ch < nchunks; ch++) {
        const int k0 = ch * TC_BK;
        // ---- load + bf16 hi/lo convert: A tile ----
        {
            const float* src = A + (size_t)bm * K + k0;
#pragma unroll
            for (int pass = 0; pass < 8; pass++) {
                int row = pass * 16 + r0;
                float4 f = *(const float4*)(src + (size_t)row * K + c4 * 4);
                __nv_bfloat16 hx = __float2bfloat16(f.x), hy = __float2bfloat16(f.y);
                __nv_bfloat16 hz = __float2bfloat16(f.z), hw = __float2bfloat16(f.w);
                __nv_bfloat16 lx = __float2bfloat16(f.x - __bfloat162float(hx));
                __nv_bfloat16 ly = __float2bfloat16(f.y - __bfloat162float(hy));
                __nv_bfloat16 lz = __float2bfloat16(f.z - __bfloat162float(hz));
                __nv_bfloat16 lw = __float2bfloat16(f.w - __bfloat162float(hw));
                __nv_bfloat162 h01 = __halves2bfloat162(hx, hy);
                __nv_bfloat162 h23 = __halves2bfloat162(hz, hw);
                __nv_bfloat162 l01 = __halves2bfloat162(lx, ly);
                __nv_bfloat162 l23 = __halves2bfloat162(lz, lw);
                uint32_t off = row * 128 + c4 * 8;
                uint32_t swz = off ^ ((off >> 3) & 0x70);
                *(uint2*)(p_ah + swz) = make_uint2(*(uint32_t*)&h01, *(uint32_t*)&h23);
                *(uint2*)(p_al + swz) = make_uint2(*(uint32_t*)&l01, *(uint32_t*)&l23);
            }
        }
        // ---- load + convert: B tile ----
        {
            const float* src = B + (size_t)bn * K + k0;
#pragma unroll
            for (int pass = 0; pass < 8; pass++) {
                int row = pass * 16 + r0;
                float4 f = *(const float4*)(src + (size_t)row * K + c4 * 4);
                __nv_bfloat16 hx = __float2bfloat16(f.x), hy = __float2bfloat16(f.y);
                __nv_bfloat16 hz = __float2bfloat16(f.z), hw = __float2bfloat16(f.w);
                __nv_bfloat16 lx = __float2bfloat16(f.x - __bfloat162float(hx));
                __nv_bfloat16 ly = __float2bfloat16(f.y - __bfloat162float(hy));
                __nv_bfloat16 lz = __float2bfloat16(f.z - __bfloat162float(hz));
                __nv_bfloat16 lw = __float2bfloat16(f.w - __bfloat162float(hw));
                __nv_bfloat162 h01 = __halves2bfloat162(hx, hy);
                __nv_bfloat162 h23 = __halves2bfloat162(hz, hw);
                __nv_bfloat162 l01 = __halves2bfloat162(lx, ly);
                __nv_bfloat162 l23 = __halves2bfloat162(lz, lw);
                uint32_t off = row * 128 + c4 * 8;
                uint32_t swz = off ^ ((off >> 3) & 0x70);
                *(uint2*)(p_bh + swz) = make_uint2(*(uint32_t*)&h01, *(uint32_t*)&h23);
                *(uint2*)(p_bl + swz) = make_uint2(*(uint32_t*)&l01, *(uint32_t*)&l23);
            }
        }
        asm volatile("fence.proxy.async.shared::cta;" ::: "memory");
        __syncthreads();

        // ---- issue 12 MMAs (4 k-steps x 3 split terms) ----
        if (tid == 0) {
            uint64_t adh = make_sw128_desc(S_AH), adl = make_sw128_desc(S_AL);
            uint64_t bdh = make_sw128_desc(S_BH), bdl = make_sw128_desc(S_BL);
#pragma unroll
            for (int ks = 0; ks < 4; ks++) {
                mma_ss_bf16(tmem, adh + ks * 2, bdh + ks * 2, (ch != 0 || ks != 0));
                mma_ss_bf16(tmem, adl + ks * 2, bdh + ks * 2, 1u);
                mma_ss_bf16(tmem, adh + ks * 2, bdl + ks * 2, 1u);
            }
            asm volatile(
                "tcgen05.commit.cta_group::1.mbarrier::arrive::one.shared::cluster.b64 [%0];"
                :: "r"(MBAR) : "memory");
        }
        // all threads wait for MMA completion before overwriting smem
        mbar_wait_parity(MBAR, (uint32_t)(ch & 1));
    }

    asm volatile("tcgen05.fence::after_thread_sync;" ::: "memory");

    // ---- epilogue: warps 0-3 read TMEM (128 lanes) and store fp32 C ----
    if (wid < 4) {
        int m = bm + wid * 32 + lid;
        float* cp = C + (size_t)m * N + bn;
#pragma unroll
        for (int base = 0; base < 128; base += 32) {
            uint32_t r[32];
            tmem_ld32(r, tmem + base);
            asm volatile("tcgen05.wait::ld.sync.aligned;" ::: "memory");
#pragma unroll
            for (int j = 0; j < 32; j += 4) {
                float4 v = make_float4(__uint_as_float(r[j]), __uint_as_float(r[j + 1]),
                                       __uint_as_float(r[j + 2]), __uint_as_float(r[j + 3]));
                *(float4*)(cp + base + j) = v;
            }
        }
    }
    __syncthreads();
    if (tid == 0)
        asm volatile("mbarrier.inval.shared.b64 [%0];" :: "r"(MBAR) : "memory");
    __syncthreads();
    if (wid == 0) {
        asm volatile("tcgen05.relinquish_alloc_permit.cta_group::1.sync.aligned;");
        asm volatile("tcgen05.dealloc.cta_group::1.sync.aligned.b32 %0, %1;"
                     :: "r"(tmem), "r"(128u));
    }
#endif // TC_OK
}

// ============================================================
// Depthwise causal conv (width 4) + bias + silu over xs half of g_xr
// ============================================================
__global__ void conv_silu_kernel(const float* __restrict__ conv_w,
                                 const float* __restrict__ conv_b)
{
    int idx = blockIdx.x * blockDim.x + threadIdx.x;
    if (idx >= MROWS * INNER) return;
    int c = idx & (INNER - 1);
    int m = idx >> 11;
    int l = m & (LSEQ - 1);
    float w0 = conv_w[c * 4 + 0], w1 = conv_w[c * 4 + 1];
    float w2 = conv_w[c * 4 + 2], w3 = conv_w[c * 4 + 3];
    float s = conv_b[c];
    s = fmaf(w3, g_xr[(size_t)m * NIN + c], s);
    if (l >= 1) s = fmaf(w2, g_xr[(size_t)(m - 1) * NIN + c], s);
    if (l >= 2) s = fmaf(w1, g_xr[(size_t)(m - 2) * NIN + c], s);
    if (l >= 3) s = fmaf(w0, g_xr[(size_t)(m - 3) * NIN + c], s);
    float sig = 1.f / (1.f + __expf(-s));
    g_xs[idx] = s * sig;
}

// ============================================================
// x_dbl[M,96] = g_xs[M,2048] @ W_x[96,2048]^T
// ============================================================
__global__ void xdbl_kernel(const float* __restrict__ W_x)
{
    __shared__ float xsh[16][128];
    int j = threadIdx.x;
    int y = threadIdx.y;
    int rb = blockIdx.x * 16;
    float acc[4] = {0.f, 0.f, 0.f, 0.f};
    int t = y * 96 + j;
    for (int k0 = 0; k0 < INNER; k0 += 128) {
        for (int e = t; e < 16 * 128; e += 384) {
            int rr = e >> 7, kk = e & 127;
            xsh[rr][kk] = g_xs[(size_t)(rb + rr) * INNER + k0 + kk];
        }
        __syncthreads();
        const float* wrow = W_x + (size_t)j * INNER + k0;
#pragma unroll 4
        for (int kk = 0; kk < 128; kk++) {
            float w = wrow[kk];
            acc[0] = fmaf(xsh[y + 0][kk], w, acc[0]);
            acc[1] = fmaf(xsh[y + 4][kk], w, acc[1]);
            acc[2] = fmaf(xsh[y + 8][kk], w, acc[2]);
            acc[3] = fmaf(xsh[y + 12][kk], w, acc[3]);
        }
        __syncthreads();
    }
#pragma unroll
    for (int i = 0; i < 4; i++)
        g_xdbl[(size_t)(rb + y + 4 * i) * XD + j] = acc[i];
}

// ============================================================
// dt2 = softplus(softplus(x_dbl[:, :64] @ W_dt^T + b_dt))
// ============================================================
__global__ __launch_bounds__(256) void dt_kernel(const float* __restrict__ W_dt,
                                                 const float* __restrict__ b_dt)
{
    __shared__ float Xs[64][65];
    __shared__ float Ws[64][65];
    int tid = threadIdx.x;
    int rb = blockIdx.y * 64, cb = blockIdx.x * 64;
    for (int e = tid; e < 64 * 64; e += 256) {
        int r = e >> 6, k = e & 63;
        Xs[r][k] = g_xdbl[(size_t)(rb + r) * XD + k];
        Ws[r][k] = W_dt[(size_t)(cb + r) * DTR + k];
    }
    __syncthreads();
    int tx = tid & 15, ty = tid >> 4;
    float acc[4][4];
#pragma unroll
    for (int i = 0; i < 4; i++)
#pragma unroll
        for (int j = 0; j < 4; j++) acc[i][j] = 0.f;
#pragma unroll 8
    for (int k = 0; k < 64; k++) {
        float a[4], b[4];
#pragma unroll
        for (int i = 0; i < 4; i++) { a[i] = Xs[ty * 4 + i][k]; b[i] = Ws[tx * 4 + i][k]; }
#pragma unroll
        for (int i = 0; i < 4; i++)
#pragma unroll
            for (int j = 0; j < 4; j++)
                acc[i][j] = fmaf(a[i], b[j], acc[i][j]);
    }
#pragma unroll
    for (int i = 0; i < 4; i++)
#pragma unroll
        for (int j = 0; j < 4; j++) {
            int r = rb + ty * 4 + i, d = cb + tx * 4 + j;
            float v = acc[i][j] + b_dt[d];
            v = softplusf(v);      // dt
            v = softplusf(v);      // dt2 (reference double-softplus)
            g_dt[(size_t)r * INNER + d] = v;
        }
}

// ============================================================
// Selective scan. 16-lane group per channel (2 channels / warp).
// ============================================================
__global__ __launch_bounds__(256) void scan_kernel(const float* __restrict__ A_log,
                                                   const float* __restrict__ D_par)
{
    int w = blockIdx.x * 8 + (threadIdx.x >> 5);
    int lane = threadIdx.x & 31;
    int b = w >> 10;
    int pair = w & 1023;
    int d = pair * 2 + ((lane >> 4) & 1);
    int n = lane & 15;

    float a = -__expf(A_log[d * DST + n]);
    float Dv = D_par[d];
    float h = 0.f;

    size_t base = (size_t)b * LSEQ;
    for (int t = 0; t < LSEQ; t++) {
        size_t m = base + t;
        float dt = g_dt[m * INNER + d];
        float xv = g_xs[m * INNER + d];
        float Bn = g_xdbl[m * XD + DTR + n];
        float Cn = g_xdbl[m * XD + DTR + DST + n];
        float dA = __expf(dt * a);
        h = fmaf(dA, h, dt * Bn * xv);
        float pv = h * Cn;
        pv += __shfl_xor_sync(0xffffffffu, pv, 8);
        pv += __shfl_xor_sync(0xffffffffu, pv, 4);
        pv += __shfl_xor_sync(0xffffffffu, pv, 2);
        pv += __shfl_xor_sync(0xffffffffu, pv, 1);
        if (n == 0) {
            float resv = g_xr[m * NIN + INNER + d];
            float silu_r = resv / (1.f + __expf(-resv));
            g_y[m * INNER + d] = (pv + xv * Dv) * silu_r;
        }
    }
}

// ============================================================
extern "C" void kernel_launch(void* const* d_in, const int* in_sizes, int n_in,
                              void* d_out, int out_size)
{
    const float* x      = (const float*)d_in[0];
    const float* W_in   = (const float*)d_in[1];
    const float* conv_w = (const float*)d_in[2];
    const float* conv_b = (const float*)d_in[3];
    const float* W_x    = (const float*)d_in[4];
    const float* W_dt   = (const float*)d_in[5];
    const float* b_dt   = (const float*)d_in[6];
    const float* A_log  = (const float*)d_in[7];
    const float* D_par  = (const float*)d_in[8];
    const float* W_out  = (const float*)d_in[9];
    float* out = (float*)d_out;

    float *xr_p, *y_p;
    cudaGetSymbolAddress((void**)&xr_p, g_xr);
    cudaGetSymbolAddress((void**)&y_p,  g_y);

    cudaFuncSetAttribute(tc_gemm_nt,
                         cudaFuncAttributeMaxDynamicSharedMemorySize, TC_SMEM_BYTES);

    // 1) xr = x @ W_in^T  (tcgen05, 3-term bf16 split)
    tc_gemm_nt<<<dim3(NIN / TC_BN, MROWS / TC_BM), 256, TC_SMEM_BYTES>>>(
        x, W_in, xr_p, MROWS, NIN, DMODEL);

    // 2) depthwise causal conv + silu -> g_xs
    conv_silu_kernel<<<(MROWS * INNER + 255) / 256, 256>>>(conv_w, conv_b);

    // 3) x_dbl = xs @ W_x^T  [4096,96]
    xdbl_kernel<<<MROWS / 16, dim3(96, 4)>>>(W_x);

    // 4) dt2 = softplus(softplus(x_dbl[:,:64] @ W_dt^T + b_dt))
    dt_kernel<<<dim3(INNER / 64, MROWS / 64), 256>>>(W_dt, b_dt);

    // 5) selective scan + fused epilogue -> g_y
    scan_kernel<<<256, 256>>>(A_log, D_par);

    // 6) out = y @ W_out^T  (tcgen05)
    tc_gemm_nt<<<dim3(DMODEL / TC_BN, MROWS / TC_BM), 256, TC_SMEM_BYTES>>>(
        y_p, W_out, out, MROWS, DMODEL, INNER);
}

// round 10
// speedup vs baseline: 1.9718x; 1.5401x over previous
#include <cuda_runtime.h>
#include <cuda_bf16.h>
#include <math.h>
#include <stdint.h>

#define BSZ    2
#define LSEQ   2048
#define DMODEL 1024
#define INNER  2048
#define MROWS  4096      // BSZ*LSEQ
#define NIN    4096      // 2*INNER
#define DTR    64
#define DST    16
#define XD     96        // DTR + 2*DST

// tcgen05 PTX is only legal in the arch-specific target pass (sm_103a).
// The harness also emits a plain compute_103 pass; give it an empty body.
#if defined(__CUDA_ARCH_FEAT_SM103_ALL) || defined(__CUDA_ARCH_FEAT_SM100_ALL)
#define TC_OK 1
#else
#define TC_OK 0
#endif

// ---- scratch (device globals; no allocation allowed) ----
__device__ float g_xr[(size_t)MROWS * NIN];     // x @ W_in^T  (xs | res)
__device__ float g_xs[(size_t)MROWS * INNER];   // conv+silu output
__device__ float g_xdbl[(size_t)MROWS * XD];    // xs @ W_x^T
__device__ float g_dt[(size_t)MROWS * INNER];   // dt2
// bf16 hi/lo split planes (converted ONCE, consumed by tcgen05 GEMMs)
__device__ __align__(16) __nv_bfloat16 g_xh[(size_t)MROWS * DMODEL];
__device__ __align__(16) __nv_bfloat16 g_xl[(size_t)MROWS * DMODEL];
__device__ __align__(16) __nv_bfloat16 g_wih[(size_t)NIN * DMODEL];
__device__ __align__(16) __nv_bfloat16 g_wil[(size_t)NIN * DMODEL];
__device__ __align__(16) __nv_bfloat16 g_woh[(size_t)DMODEL * INNER];
__device__ __align__(16) __nv_bfloat16 g_wol[(size_t)DMODEL * INNER];
__device__ __align__(16) __nv_bfloat16 g_yh[(size_t)MROWS * INNER];
__device__ __align__(16) __nv_bfloat16 g_yl[(size_t)MROWS * INNER];

__device__ __forceinline__ float softplusf(float x) {
    return fmaxf(x, 0.f) + __logf(1.f + __expf(-fabsf(x)));
}

// ============================================================
// fp32 -> bf16 hi/lo split planes (one pass, memory-bound)
// ============================================================
__global__ void split_bf16_kernel(const float4* __restrict__ src,
                                  __nv_bfloat162* __restrict__ hi,
                                  __nv_bfloat162* __restrict__ lo, int n4)
{
    int i = blockIdx.x * blockDim.x + threadIdx.x;
    if (i >= n4) return;
    float4 f = src[i];
    __nv_bfloat16 hx = __float2bfloat16(f.x), hy = __float2bfloat16(f.y);
    __nv_bfloat16 hz = __float2bfloat16(f.z), hw = __float2bfloat16(f.w);
    __nv_bfloat16 lx = __float2bfloat16(f.x - __bfloat162float(hx));
    __nv_bfloat16 ly = __float2bfloat16(f.y - __bfloat162float(hy));
    __nv_bfloat16 lz = __float2bfloat16(f.z - __bfloat162float(hz));
    __nv_bfloat16 lw = __float2bfloat16(f.w - __bfloat162float(hw));
    hi[i * 2 + 0] = __halves2bfloat162(hx, hy);
    hi[i * 2 + 1] = __halves2bfloat162(hz, hw);
    lo[i * 2 + 0] = __halves2bfloat162(lx, ly);
    lo[i * 2 + 1] = __halves2bfloat162(lz, lw);
}

// ============================================================
// tcgen05 bf16 split-GEMM with cp.async double-buffered pipeline.
// C[M,N] = (Ah+Al)[M,K] * (Bh+Bl)[N,K]^T (3-term split), fp32 out.
// Tile 128x128; K-chunks of 64 bf16 (128B rows, SW128); 2 stages.
// ============================================================
#define TC_BM 128
#define TC_BN 128
#define TC_BK 64
#define TC_TILE_BYTES 16384                       // 128 rows * 128 bytes
#define TC_STAGE_BYTES (4 * TC_TILE_BYTES)        // ah|al|bh|bl = 64KB
#define TC_SMEM_BYTES (1024 + 2 * TC_STAGE_BYTES) // 132096
#define TC_IDESC 0x8200490u                       // F32 acc, BF16xBF16, M=128, N=128

__device__ __forceinline__ uint32_t smem_u32(const void* p) {
    uint32_t a;
    asm("{ .reg .u64 t; cvta.to.shared.u64 t, %1; cvt.u32.u64 %0, t; }"
        : "=r"(a) : "l"(p));
    return a;
}

#if TC_OK
__device__ __forceinline__ uint64_t make_sw128_desc(uint32_t addr) {
    return ( (uint64_t)2 << 61 ) | ( (uint64_t)1 << 46 )
         | ( (uint64_t)64 << 32 ) | ( (uint64_t)1 << 16 )
         | ( (uint64_t)(addr >> 4) & 0x3FFF );
}

__device__ __forceinline__ void mma_ss_bf16(uint32_t d, uint64_t ad, uint64_t bd,
                                            uint32_t acc) {
    asm volatile(
        "{\n\t.reg .pred p;\n\t"
        "setp.ne.u32 p, %4, 0;\n\t"
        "tcgen05.mma.cta_group::1.kind::f16 [%0], %1, %2, %3, {%5, %5, %5, %5}, p;\n\t}"
        :: "r"(d), "l"(ad), "l"(bd), "r"(TC_IDESC), "r"(acc), "r"(0u)
        : "memory");
}

__device__ __forceinline__ void mbar_wait_parity(uint32_t mbar, uint32_t parity) {
    asm volatile(
        "{\n\t.reg .pred P;\n\t"
        "WL_%=:\n\t"
        "mbarrier.try_wait.parity.acquire.cta.shared::cta.b64 P, [%0], %1, 0x989680;\n\t"
        "@!P bra WL_%=;\n\t}"
        :: "r"(mbar), "r"(parity) : "memory");
}

__device__ __forceinline__ void tmem_ld32(uint32_t* r, uint32_t addr) {
    asm volatile(
        "tcgen05.ld.sync.aligned.32x32b.x32.b32 "
        "{%0, %1, %2, %3, %4, %5, %6, %7, "
        " %8, %9, %10, %11, %12, %13, %14, %15, "
        " %16, %17, %18, %19, %20, %21, %22, %23, "
        " %24, %25, %26, %27, %28, %29, %30, %31}, [%32];"
        : "=r"(r[0]), "=r"(r[1]), "=r"(r[2]), "=r"(r[3]),
          "=r"(r[4]), "=r"(r[5]), "=r"(r[6]), "=r"(r[7]),
          "=r"(r[8]), "=r"(r[9]), "=r"(r[10]), "=r"(r[11]),
          "=r"(r[12]), "=r"(r[13]), "=r"(r[14]), "=r"(r[15]),
          "=r"(r[16]), "=r"(r[17]), "=r"(r[18]), "=r"(r[19]),
          "=r"(r[20]), "=r"(r[21]), "=r"(r[22]), "=r"(r[23]),
          "=r"(r[24]), "=r"(r[25]), "=r"(r[26]), "=r"(r[27]),
          "=r"(r[28]), "=r"(r[29]), "=r"(r[30]), "=r"(r[31])
        : "r"(addr));
}

// copy one 128x64 bf16 tile (K-major) into SW128-swizzled smem via cp.async
__device__ __forceinline__ void copy_tile(const __nv_bfloat16* __restrict__ plane,
                                          int row0, int k0, int K,
                                          uint32_t dst, int tid)
{
#pragma unroll
    for (int p = 0; p < 4; p++) {
        int idx = p * 256 + tid;       // 0..1023
        int r = idx >> 3;              // row 0..127
        int b = (idx & 7) << 4;        // byte offset in 128B row
        uint32_t off = (uint32_t)(r * 128 + b);
        uint32_t swz = off ^ ((off >> 3) & 0x70);
        const void* src = plane + (size_t)(row0 + r) * K + k0 + (b >> 1);
        asm volatile("cp.async.cg.shared.global [%0], [%1], 16;"
                     :: "r"(dst + swz), "l"(src) : "memory");
    }
}
#endif // TC_OK

__global__ __launch_bounds__(256) void tc_gemm_split(
    const __nv_bfloat16* __restrict__ Ah, const __nv_bfloat16* __restrict__ Al,
    const __nv_bfloat16* __restrict__ Bh, const __nv_bfloat16* __restrict__ Bl,
    float* __restrict__ C, int M, int N, int K)
{
#if TC_OK
    extern __shared__ char smem[];
    const uint32_t sb = smem_u32(smem);
    const uint32_t MBAR0 = sb + 8;    // stage-0 MMA-done
    const uint32_t MBAR1 = sb + 16;   // stage-1 MMA-done
    const uint32_t DONE  = sb + 24;   // final drain
    const uint32_t S_DATA = sb + 1024;

    const int tid = threadIdx.x;
    const int wid = tid >> 5, lid = tid & 31;
    const int bm = blockIdx.y * TC_BM;
    const int bn = blockIdx.x * TC_BN;

    if (wid == 0) {
        asm volatile(
            "tcgen05.alloc.cta_group::1.sync.aligned.shared::cta.b32 [%0], %1;"
            :: "r"(sb), "r"(128u) : "memory");
    }
    if (tid == 0) {
        asm volatile("mbarrier.init.shared.b64 [%0], 1;" :: "r"(MBAR0) : "memory");
        asm volatile("mbarrier.init.shared.b64 [%0], 1;" :: "r"(MBAR1) : "memory");
        asm volatile("mbarrier.init.shared.b64 [%0], 1;" :: "r"(DONE)  : "memory");
    }
    __syncthreads();
    uint32_t tmem;
    asm volatile("ld.shared.b32 %0, [%1];" : "=r"(tmem) : "r"(sb));

    const int nch = K / TC_BK;

    // prologue: copy chunk 0 into stage 0
    {
        uint32_t st = S_DATA;
        copy_tile(Ah, bm, 0, K, st + 0 * TC_TILE_BYTES, tid);
        copy_tile(Al, bm, 0, K, st + 1 * TC_TILE_BYTES, tid);
        copy_tile(Bh, bn, 0, K, st + 2 * TC_TILE_BYTES, tid);
        copy_tile(Bl, bn, 0, K, st + 3 * TC_TILE_BYTES, tid);
        asm volatile("cp.async.commit_group;" ::: "memory");
    }

    for (int ch = 0; ch < nch; ch++) {
        const int s = ch & 1;
        if (ch + 1 < nch) {
            const int nx = ch + 1, t = nx & 1;
            if (nx >= 2) {
                // stage t last used by MMA(nx-2); wait its commit
                uint32_t py = (uint32_t)(((nx - 2 - t) >> 1) & 1);
                mbar_wait_parity(t ? MBAR1 : MBAR0, py);
            }
            const int k0 = nx * TC_BK;
            uint32_t st = S_DATA + (uint32_t)t * TC_STAGE_BYTES;
            copy_tile(Ah, bm, k0, K, st + 0 * TC_TILE_BYTES, tid);
            copy_tile(Al, bm, k0, K, st + 1 * TC_TILE_BYTES, tid);
            copy_tile(Bh, bn, k0, K, st + 2 * TC_TILE_BYTES, tid);
            copy_tile(Bl, bn, k0, K, st + 3 * TC_TILE_BYTES, tid);
            asm volatile("cp.async.commit_group;" ::: "memory");
            asm volatile("cp.async.wait_group 1;" ::: "memory");  // chunk ch landed
        } else {
            asm volatile("cp.async.wait_group 0;" ::: "memory");
        }
        asm volatile("fence.proxy.async.shared::cta;" ::: "memory");
        __syncthreads();

        if (tid == 0) {
            uint32_t base = S_DATA + (uint32_t)s * TC_STAGE_BYTES;
            uint64_t adh = make_sw128_desc(base);
            uint64_t adl = make_sw128_desc(base + 1 * TC_TILE_BYTES);
            uint64_t bdh = make_sw128_desc(base + 2 * TC_TILE_BYTES);
            uint64_t bdl = make_sw128_desc(base + 3 * TC_TILE_BYTES);
#pragma unroll
            for (int ks = 0; ks < 4; ks++) {
                mma_ss_bf16(tmem, adh + ks * 2, bdh + ks * 2,
                            (uint32_t)(ch != 0 || ks != 0));
                mma_ss_bf16(tmem, adl + ks * 2, bdh + ks * 2, 1u);
                mma_ss_bf16(tmem, adh + ks * 2, bdl + ks * 2, 1u);
            }
            asm volatile(
                "tcgen05.commit.cta_group::1.mbarrier::arrive::one.shared::cluster.b64 [%0];"
                :: "r"(s ? MBAR1 : MBAR0) : "memory");
        }
    }

    // drain: one commit covering all prior MMAs
    if (tid == 0) {
        asm volatile(
            "tcgen05.commit.cta_group::1.mbarrier::arrive::one.shared::cluster.b64 [%0];"
            :: "r"(DONE) : "memory");
    }
    mbar_wait_parity(DONE, 0);
    asm volatile("tcgen05.fence::after_thread_sync;" ::: "memory");

    // epilogue: warps 0-3 read TMEM (128 lanes) and store fp32 C
    if (wid < 4) {
        int m = bm + wid * 32 + lid;
        float* cp = C + (size_t)m * N + bn;
#pragma unroll
        for (int base = 0; base < 128; base += 32) {
            uint32_t r[32];
            tmem_ld32(r, tmem + base);
            asm volatile("tcgen05.wait::ld.sync.aligned;" ::: "memory");
#pragma unroll
            for (int j = 0; j < 32; j += 4) {
                float4 v = make_float4(__uint_as_float(r[j]), __uint_as_float(r[j + 1]),
                                       __uint_as_float(r[j + 2]), __uint_as_float(r[j + 3]));
                *(float4*)(cp + base + j) = v;
            }
        }
    }
    __syncthreads();
    if (tid == 0) {
        asm volatile("mbarrier.inval.shared.b64 [%0];" :: "r"(MBAR0) : "memory");
        asm volatile("mbarrier.inval.shared.b64 [%0];" :: "r"(MBAR1) : "memory");
        asm volatile("mbarrier.inval.shared.b64 [%0];" :: "r"(DONE)  : "memory");
    }
    __syncthreads();
    if (wid == 0) {
        asm volatile("tcgen05.relinquish_alloc_permit.cta_group::1.sync.aligned;");
        asm volatile("tcgen05.dealloc.cta_group::1.sync.aligned.b32 %0, %1;"
                     :: "r"(tmem), "r"(128u));
    }
#endif // TC_OK
}

// ============================================================
// Depthwise causal conv (width 4) + bias + silu over xs half of g_xr
// ============================================================
__global__ void conv_silu_kernel(const float* __restrict__ conv_w,
                                 const float* __restrict__ conv_b)
{
    int idx = blockIdx.x * blockDim.x + threadIdx.x;
    if (idx >= MROWS * INNER) return;
    int c = idx & (INNER - 1);
    int m = idx >> 11;
    int l = m & (LSEQ - 1);
    float w0 = conv_w[c * 4 + 0], w1 = conv_w[c * 4 + 1];
    float w2 = conv_w[c * 4 + 2], w3 = conv_w[c * 4 + 3];
    float s = conv_b[c];
    s = fmaf(w3, g_xr[(size_t)m * NIN + c], s);
    if (l >= 1) s = fmaf(w2, g_xr[(size_t)(m - 1) * NIN + c], s);
    if (l >= 2) s = fmaf(w1, g_xr[(size_t)(m - 2) * NIN + c], s);
    if (l >= 3) s = fmaf(w0, g_xr[(size_t)(m - 3) * NIN + c], s);
    float sig = 1.f / (1.f + __expf(-s));
    g_xs[idx] = s * sig;
}

// ============================================================
// x_dbl[M,96] = g_xs[M,2048] @ W_x[96,2048]^T
// ============================================================
__global__ void xdbl_kernel(const float* __restrict__ W_x)
{
    __shared__ float xsh[16][128];
    int j = threadIdx.x;
    int y = threadIdx.y;
    int rb = blockIdx.x * 16;
    float acc[4] = {0.f, 0.f, 0.f, 0.f};
    int t = y * 96 + j;
    for (int k0 = 0; k0 < INNER; k0 += 128) {
        for (int e = t; e < 16 * 128; e += 384) {
            int rr = e >> 7, kk = e & 127;
            xsh[rr][kk] = g_xs[(size_t)(rb + rr) * INNER + k0 + kk];
        }
        __syncthreads();
        const float* wrow = W_x + (size_t)j * INNER + k0;
#pragma unroll 4
        for (int kk = 0; kk < 128; kk++) {
            float w = wrow[kk];
            acc[0] = fmaf(xsh[y + 0][kk], w, acc[0]);
            acc[1] = fmaf(xsh[y + 4][kk], w, acc[1]);
            acc[2] = fmaf(xsh[y + 8][kk], w, acc[2]);
            acc[3] = fmaf(xsh[y + 12][kk], w, acc[3]);
        }
        __syncthreads();
    }
#pragma unroll
    for (int i = 0; i < 4; i++)
        g_xdbl[(size_t)(rb + y + 4 * i) * XD + j] = acc[i];
}

// ============================================================
// dt2 = softplus(softplus(x_dbl[:, :64] @ W_dt^T + b_dt))
// ============================================================
__global__ __launch_bounds__(256) void dt_kernel(const float* __restrict__ W_dt,
                                                 const float* __restrict__ b_dt)
{
    __shared__ float Xs[64][65];
    __shared__ float Ws[64][65];
    int tid = threadIdx.x;
    int rb = blockIdx.y * 64, cb = blockIdx.x * 64;
    for (int e = tid; e < 64 * 64; e += 256) {
        int r = e >> 6, k = e & 63;
        Xs[r][k] = g_xdbl[(size_t)(rb + r) * XD + k];
        Ws[r][k] = W_dt[(size_t)(cb + r) * DTR + k];
    }
    __syncthreads();
    int tx = tid & 15, ty = tid >> 4;
    float acc[4][4];
#pragma unroll
    for (int i = 0; i < 4; i++)
#pragma unroll
        for (int j = 0; j < 4; j++) acc[i][j] = 0.f;
#pragma unroll 8
    for (int k = 0; k < 64; k++) {
        float a[4], b[4];
#pragma unroll
        for (int i = 0; i < 4; i++) { a[i] = Xs[ty * 4 + i][k]; b[i] = Ws[tx * 4 + i][k]; }
#pragma unroll
        for (int i = 0; i < 4; i++)
#pragma unroll
            for (int j = 0; j < 4; j++)
                acc[i][j] = fmaf(a[i], b[j], acc[i][j]);
    }
#pragma unroll
    for (int i = 0; i < 4; i++)
#pragma unroll
        for (int j = 0; j < 4; j++) {
            int r = rb + ty * 4 + i, d = cb + tx * 4 + j;
            float v = acc[i][j] + b_dt[d];
            v = softplusf(v);      // dt
            v = softplusf(v);      // dt2 (reference double-softplus)
            g_dt[(size_t)r * INNER + d] = v;
        }
}

// ============================================================
// Selective scan + fused epilogue; writes y directly as bf16 hi/lo planes
// (feeds GEMM2 without an extra conversion pass).
// ============================================================
__global__ __launch_bounds__(256) void scan_kernel(const float* __restrict__ A_log,
                                                   const float* __restrict__ D_par)
{
    int w = blockIdx.x * 8 + (threadIdx.x >> 5);
    int lane = threadIdx.x & 31;
    int b = w >> 10;
    int pair = w & 1023;
    int d = pair * 2 + ((lane >> 4) & 1);
    int n = lane & 15;

    float a = -__expf(A_log[d * DST + n]);
    float Dv = D_par[d];
    float h = 0.f;

    size_t base = (size_t)b * LSEQ;
    for (int t = 0; t < LSEQ; t++) {
        size_t m = base + t;
        float dt = g_dt[m * INNER + d];
        float xv = g_xs[m * INNER + d];
        float Bn = g_xdbl[m * XD + DTR + n];
        float Cn = g_xdbl[m * XD + DTR + DST + n];
        float dA = __expf(dt * a);
        h = fmaf(dA, h, dt * Bn * xv);
        float pv = h * Cn;
        pv += __shfl_xor_sync(0xffffffffu, pv, 8);
        pv += __shfl_xor_sync(0xffffffffu, pv, 4);
        pv += __shfl_xor_sync(0xffffffffu, pv, 2);
        pv += __shfl_xor_sync(0xffffffffu, pv, 1);
        if (n == 0) {
            float resv = g_xr[m * NIN + INNER + d];
            float silu_r = resv / (1.f + __expf(-resv));
            float v = (pv + xv * Dv) * silu_r;
            __nv_bfloat16 vh = __float2bfloat16(v);
            __nv_bfloat16 vl = __float2bfloat16(v - __bfloat162float(vh));
            g_yh[m * INNER + d] = vh;
            g_yl[m * INNER + d] = vl;
        }
    }
}

// ============================================================
extern "C" void kernel_launch(void* const* d_in, const int* in_sizes, int n_in,
                              void* d_out, int out_size)
{
    const float* x      = (const float*)d_in[0];
    const float* W_in   = (const float*)d_in[1];
    const float* conv_w = (const float*)d_in[2];
    const float* conv_b = (const float*)d_in[3];
    const float* W_x    = (const float*)d_in[4];
    const float* W_dt   = (const float*)d_in[5];
    const float* b_dt   = (const float*)d_in[6];
    const float* A_log  = (const float*)d_in[7];
    const float* D_par  = (const float*)d_in[8];
    const float* W_out  = (const float*)d_in[9];
    float* out = (float*)d_out;

    float *xr_p;
    __nv_bfloat16 *xh_p, *xl_p, *wih_p, *wil_p, *woh_p, *wol_p, *yh_p, *yl_p;
    cudaGetSymbolAddress((void**)&xr_p,  g_xr);
    cudaGetSymbolAddress((void**)&xh_p,  g_xh);
    cudaGetSymbolAddress((void**)&xl_p,  g_xl);
    cudaGetSymbolAddress((void**)&wih_p, g_wih);
    cudaGetSymbolAddress((void**)&wil_p, g_wil);
    cudaGetSymbolAddress((void**)&woh_p, g_woh);
    cudaGetSymbolAddress((void**)&wol_p, g_wol);
    cudaGetSymbolAddress((void**)&yh_p,  g_yh);
    cudaGetSymbolAddress((void**)&yl_p,  g_yl);

    cudaFuncSetAttribute(tc_gemm_split,
                         cudaFuncAttributeMaxDynamicSharedMemorySize, TC_SMEM_BYTES);

    // 0) one-time bf16 hi/lo splits (memory-bound)
    {
        int n4 = (MROWS * DMODEL) / 4;
        split_bf16_kernel<<<(n4 + 255) / 256, 256>>>(
            (const float4*)x, (__nv_bfloat162*)xh_p, (__nv_bfloat162*)xl_p, n4);
        n4 = (NIN * DMODEL) / 4;
        split_bf16_kernel<<<(n4 + 255) / 256, 256>>>(
            (const float4*)W_in, (__nv_bfloat162*)wih_p, (__nv_bfloat162*)wil_p, n4);
        n4 = (DMODEL * INNER) / 4;
        split_bf16_kernel<<<(n4 + 255) / 256, 256>>>(
            (const float4*)W_out, (__nv_bfloat162*)woh_p, (__nv_bfloat162*)wol_p, n4);
    }

    // 1) xr = x @ W_in^T  (tcgen05, pipelined)
    tc_gemm_split<<<dim3(NIN / TC_BN, MROWS / TC_BM), 256, TC_SMEM_BYTES>>>(
        xh_p, xl_p, wih_p, wil_p, xr_p, MROWS, NIN, DMODEL);

    // 2) depthwise causal conv + silu -> g_xs
    conv_silu_kernel<<<(MROWS * INNER + 255) / 256, 256>>>(conv_w, conv_b);

    // 3) x_dbl = xs @ W_x^T  [4096,96]
    xdbl_kernel<<<MROWS / 16, dim3(96, 4)>>>(W_x);

    // 4) dt2 = softplus(softplus(x_dbl[:,:64] @ W_dt^T + b_dt))
    dt_kernel<<<dim3(INNER / 64, MROWS / 64), 256>>>(W_dt, b_dt);

    // 5) selective scan + fused epilogue -> yh/yl bf16 planes
    scan_kernel<<<256, 256>>>(A_log, D_par);

    // 6) out = y @ W_out^T  (tcgen05, pipelined)
    tc_gemm_split<<<dim3(DMODEL / TC_BN, MROWS / TC_BM), 256, TC_SMEM_BYTES>>>(
        yh_p, yl_p, woh_p, wol_p, out, MROWS, DMODEL, INNER);
}

// round 12
// speedup vs baseline: 6.2458x; 3.1676x over previous
#include <cuda_runtime.h>
#include <cuda_bf16.h>
#include <math.h>
#include <stdint.h>

#define BSZ    2
#define LSEQ   2048
#define DMODEL 1024
#define INNER  2048
#define MROWS  4096      // BSZ*LSEQ
#define NIN    4096      // 2*INNER
#define DTR    64
#define DST    16
#define XD     96        // DTR + 2*DST
#define NCHK   16        // scan chunks
#define CLEN   128       // LSEQ / NCHK

#if defined(__CUDA_ARCH_FEAT_SM103_ALL) || defined(__CUDA_ARCH_FEAT_SM100_ALL)
#define TC_OK 1
#else
#define TC_OK 0
#endif

// ---- scratch (device globals; no allocation allowed) ----
__device__ float g_xr[(size_t)MROWS * NIN];     // x @ W_in^T  (xs | res)
__device__ float g_xs[(size_t)MROWS * INNER];   // conv+silu output (fp32)
__device__ float g_xdbl[(size_t)MROWS * XD];    // xs @ W_x^T
__device__ float g_dt[(size_t)MROWS * INNER];   // dt2
// chunked-scan intermediates
__device__ float g_hc[(size_t)BSZ * NCHK * INNER * DST];   // local chunk-final h
__device__ float g_hi[(size_t)BSZ * NCHK * INNER * DST];   // chunk-initial h
__device__ float g_dts[(size_t)BSZ * NCHK * INNER];        // per-chunk sum(dt)
// bf16 hi/lo split planes (converted ONCE, consumed by tcgen05 GEMMs)
__device__ __align__(16) __nv_bfloat16 g_xh[(size_t)MROWS * DMODEL];
__device__ __align__(16) __nv_bfloat16 g_xl[(size_t)MROWS * DMODEL];
__device__ __align__(16) __nv_bfloat16 g_wih[(size_t)NIN * DMODEL];
__device__ __align__(16) __nv_bfloat16 g_wil[(size_t)NIN * DMODEL];
__device__ __align__(16) __nv_bfloat16 g_woh[(size_t)DMODEL * INNER];
__device__ __align__(16) __nv_bfloat16 g_wol[(size_t)DMODEL * INNER];
__device__ __align__(16) __nv_bfloat16 g_yh[(size_t)MROWS * INNER];
__device__ __align__(16) __nv_bfloat16 g_yl[(size_t)MROWS * INNER];
__device__ __align__(16) __nv_bfloat16 g_xsh[(size_t)MROWS * INNER];
__device__ __align__(16) __nv_bfloat16 g_xsl[(size_t)MROWS * INNER];
__device__ __align__(16) __nv_bfloat16 g_wxh[(size_t)128 * INNER];   // W_x padded 96->128 rows
__device__ __align__(16) __nv_bfloat16 g_wxl[(size_t)128 * INNER];

// ============================================================
// fp32 -> bf16 hi/lo split planes (one pass, memory-bound)
// ============================================================
__global__ void split_bf16_kernel(const float4* __restrict__ src,
                                  __nv_bfloat162* __restrict__ hi,
                                  __nv_bfloat162* __restrict__ lo, int n4)
{
    int i = blockIdx.x * blockDim.x + threadIdx.x;
    if (i >= n4) return;
    float4 f = src[i];
    __nv_bfloat16 hx = __float2bfloat16(f.x), hy = __float2bfloat16(f.y);
    __nv_bfloat16 hz = __float2bfloat16(f.z), hw = __float2bfloat16(f.w);
    __nv_bfloat16 lx = __float2bfloat16(f.x - __bfloat162float(hx));
    __nv_bfloat16 ly = __float2bfloat16(f.y - __bfloat162float(hy));
    __nv_bfloat16 lz = __float2bfloat16(f.z - __bfloat162float(hz));
    __nv_bfloat16 lw = __float2bfloat16(f.w - __bfloat162float(hw));
    hi[i * 2 + 0] = __halves2bfloat162(hx, hy);
    hi[i * 2 + 1] = __halves2bfloat162(hz, hw);
    lo[i * 2 + 0] = __halves2bfloat162(lx, ly);
    lo[i * 2 + 1] = __halves2bfloat162(lz, lw);
}

// zero the pad rows (96..127) of the W_x planes
__global__ void pad_wx_kernel()
{
    int i = blockIdx.x * blockDim.x + threadIdx.x;   // 0..65535
    if (i >= 32 * INNER) return;
    size_t o = (size_t)96 * INNER + i;
    g_wxh[o] = __float2bfloat16(0.f);
    g_wxl[o] = __float2bfloat16(0.f);
}

// ============================================================
// tcgen05 bf16 split-GEMM with cp.async double-buffered pipeline.
// C[M,ncols] = (Ah+Al)[M,K] * (Bh+Bl)[N,K]^T, fp32 out, ldC row stride.
// ============================================================
#define TC_BM 128
#define TC_BN 128
#define TC_BK 64
#define TC_TILE_BYTES 16384
#define TC_STAGE_BYTES (4 * TC_TILE_BYTES)
#define TC_SMEM_BYTES (1024 + 2 * TC_STAGE_BYTES)
#define TC_IDESC 0x8200490u

__device__ __forceinline__ uint32_t smem_u32(const void* p) {
    uint32_t a;
    asm("{ .reg .u64 t; cvta.to.shared.u64 t, %1; cvt.u32.u64 %0, t; }"
        : "=r"(a) : "l"(p));
    return a;
}

#if TC_OK
__device__ __forceinline__ uint64_t make_sw128_desc(uint32_t addr) {
    return ( (uint64_t)2 << 61 ) | ( (uint64_t)1 << 46 )
         | ( (uint64_t)64 << 32 ) | ( (uint64_t)1 << 16 )
         | ( (uint64_t)(addr >> 4) & 0x3FFF );
}

__device__ __forceinline__ void mma_ss_bf16(uint32_t d, uint64_t ad, uint64_t bd,
                                            uint32_t acc) {
    asm volatile(
        "{\n\t.reg .pred p;\n\t"
        "setp.ne.u32 p, %4, 0;\n\t"
        "tcgen05.mma.cta_group::1.kind::f16 [%0], %1, %2, %3, {%5, %5, %5, %5}, p;\n\t}"
        :: "r"(d), "l"(ad), "l"(bd), "r"(TC_IDESC), "r"(acc), "r"(0u)
        : "memory");
}

__device__ __forceinline__ void mbar_wait_parity(uint32_t mbar, uint32_t parity) {
    asm volatile(
        "{\n\t.reg .pred P;\n\t"
        "WL_%=:\n\t"
        "mbarrier.try_wait.parity.acquire.cta.shared::cta.b64 P, [%0], %1, 0x989680;\n\t"
        "@!P bra WL_%=;\n\t}"
        :: "r"(mbar), "r"(parity) : "memory");
}

__device__ __forceinline__ void tmem_ld32(uint32_t* r, uint32_t addr) {
    asm volatile(
        "tcgen05.ld.sync.aligned.32x32b.x32.b32 "
        "{%0, %1, %2, %3, %4, %5, %6, %7, "
        " %8, %9, %10, %11, %12, %13, %14, %15, "
        " %16, %17, %18, %19, %20, %21, %22, %23, "
        " %24, %25, %26, %27, %28, %29, %30, %31}, [%32];"
        : "=r"(r[0]), "=r"(r[1]), "=r"(r[2]), "=r"(r[3]),
          "=r"(r[4]), "=r"(r[5]), "=r"(r[6]), "=r"(r[7]),
          "=r"(r[8]), "=r"(r[9]), "=r"(r[10]), "=r"(r[11]),
          "=r"(r[12]), "=r"(r[13]), "=r"(r[14]), "=r"(r[15]),
          "=r"(r[16]), "=r"(r[17]), "=r"(r[18]), "=r"(r[19]),
          "=r"(r[20]), "=r"(r[21]), "=r"(r[22]), "=r"(r[23]),
          "=r"(r[24]), "=r"(r[25]), "=r"(r[26]), "=r"(r[27]),
          "=r"(r[28]), "=r"(r[29]), "=r"(r[30]), "=r"(r[31])
        : "r"(addr));
}

__device__ __forceinline__ void copy_tile(const __nv_bfloat16* __restrict__ plane,
                                          int row0, int k0, int K,
                                          uint32_t dst, int tid)
{
#pragma unroll
    for (int p = 0; p < 4; p++) {
        int idx = p * 256 + tid;
        int r = idx >> 3;
        int b = (idx & 7) << 4;
        uint32_t off = (uint32_t)(r * 128 + b);
        uint32_t swz = off ^ ((off >> 3) & 0x70);
        const void* src = plane + (size_t)(row0 + r) * K + k0 + (b >> 1);
        asm volatile("cp.async.cg.shared.global [%0], [%1], 16;"
                     :: "r"(dst + swz), "l"(src) : "memory");
    }
}
#endif // TC_OK

__global__ __launch_bounds__(256) void tc_gemm_split(
    const __nv_bfloat16* __restrict__ Ah, const __nv_bfloat16* __restrict__ Al,
    const __nv_bfloat16* __restrict__ Bh, const __nv_bfloat16* __restrict__ Bl,
    float* __restrict__ C, int M, int N, int K, int ldC, int ncols)
{
#if TC_OK
    extern __shared__ char smem[];
    const uint32_t sb = smem_u32(smem);
    const uint32_t MBAR0 = sb + 8;
    const uint32_t MBAR1 = sb + 16;
    const uint32_t DONE  = sb + 24;
    const uint32_t S_DATA = sb + 1024;

    const int tid = threadIdx.x;
    const int wid = tid >> 5, lid = tid & 31;
    const int bm = blockIdx.y * TC_BM;
    const int bn = blockIdx.x * TC_BN;

    if (wid == 0) {
        asm volatile(
            "tcgen05.alloc.cta_group::1.sync.aligned.shared::cta.b32 [%0], %1;"
            :: "r"(sb), "r"(128u) : "memory");
    }
    if (tid == 0) {
        asm volatile("mbarrier.init.shared.b64 [%0], 1;" :: "r"(MBAR0) : "memory");
        asm volatile("mbarrier.init.shared.b64 [%0], 1;" :: "r"(MBAR1) : "memory");
        asm volatile("mbarrier.init.shared.b64 [%0], 1;" :: "r"(DONE)  : "memory");
    }
    __syncthreads();
    uint32_t tmem;
    asm volatile("ld.shared.b32 %0, [%1];" : "=r"(tmem) : "r"(sb));

    const int nch = K / TC_BK;

    {
        uint32_t st = S_DATA;
        copy_tile(Ah, bm, 0, K, st + 0 * TC_TILE_BYTES, tid);
        copy_tile(Al, bm, 0, K, st + 1 * TC_TILE_BYTES, tid);
        copy_tile(Bh, bn, 0, K, st + 2 * TC_TILE_BYTES, tid);
        copy_tile(Bl, bn, 0, K, st + 3 * TC_TILE_BYTES, tid);
        asm volatile("cp.async.commit_group;" ::: "memory");
    }

    for (int ch = 0; ch < nch; ch++) {
        const int s = ch & 1;
        if (ch + 1 < nch) {
            const int nx = ch + 1, t = nx & 1;
            if (nx >= 2) {
                uint32_t py = (uint32_t)(((nx - 2 - t) >> 1) & 1);
                mbar_wait_parity(t ? MBAR1 : MBAR0, py);
            }
            const int k0 = nx * TC_BK;
            uint32_t st = S_DATA + (uint32_t)t * TC_STAGE_BYTES;
            copy_tile(Ah, bm, k0, K, st + 0 * TC_TILE_BYTES, tid);
            copy_tile(Al, bm, k0, K, st + 1 * TC_TILE_BYTES, tid);
            copy_tile(Bh, bn, k0, K, st + 2 * TC_TILE_BYTES, tid);
            copy_tile(Bl, bn, k0, K, st + 3 * TC_TILE_BYTES, tid);
            asm volatile("cp.async.commit_group;" ::: "memory");
            asm volatile("cp.async.wait_group 1;" ::: "memory");
        } else {
            asm volatile("cp.async.wait_group 0;" ::: "memory");
        }
        asm volatile("fence.proxy.async.shared::cta;" ::: "memory");
        __syncthreads();

        if (tid == 0) {
            uint32_t base = S_DATA + (uint32_t)s * TC_STAGE_BYTES;
            uint64_t adh = make_sw128_desc(base);
            uint64_t adl = make_sw128_desc(base + 1 * TC_TILE_BYTES);
            uint64_t bdh = make_sw128_desc(base + 2 * TC_TILE_BYTES);
            uint64_t bdl = make_sw128_desc(base + 3 * TC_TILE_BYTES);
#pragma unroll
            for (int ks = 0; ks < 4; ks++) {
                mma_ss_bf16(tmem, adh + ks * 2, bdh + ks * 2,
                            (uint32_t)(ch != 0 || ks != 0));
                mma_ss_bf16(tmem, adl + ks * 2, bdh + ks * 2, 1u);
                mma_ss_bf16(tmem, adh + ks * 2, bdl + ks * 2, 1u);
            }
            asm volatile(
                "tcgen05.commit.cta_group::1.mbarrier::arrive::one.shared::cluster.b64 [%0];"
                :: "r"(s ? MBAR1 : MBAR0) : "memory");
        }
    }

    if (tid == 0) {
        asm volatile(
            "tcgen05.commit.cta_group::1.mbarrier::arrive::one.shared::cluster.b64 [%0];"
            :: "r"(DONE) : "memory");
    }
    mbar_wait_parity(DONE, 0);
    asm volatile("tcgen05.fence::after_thread_sync;" ::: "memory");

    if (wid < 4) {
        int m = bm + wid * 32 + lid;
        float* cp = C + (size_t)m * ldC + bn;
#pragma unroll
        for (int base = 0; base < 128; base += 32) {
            if (bn + base >= ncols) break;
            uint32_t r[32];
            tmem_ld32(r, tmem + base);
            asm volatile("tcgen05.wait::ld.sync.aligned;" ::: "memory");
#pragma unroll
            for (int j = 0; j < 32; j += 4) {
                if (bn + base + j < ncols) {
                    float4 v = make_float4(__uint_as_float(r[j]), __uint_as_float(r[j + 1]),
                                           __uint_as_float(r[j + 2]), __uint_as_float(r[j + 3]));
                    *(float4*)(cp + base + j) = v;
                }
            }
        }
    }
    __syncthreads();
    if (tid == 0) {
        asm volatile("mbarrier.inval.shared.b64 [%0];" :: "r"(MBAR0) : "memory");
        asm volatile("mbarrier.inval.shared.b64 [%0];" :: "r"(MBAR1) : "memory");
        asm volatile("mbarrier.inval.shared.b64 [%0];" :: "r"(DONE)  : "memory");
    }
    __syncthreads();
    if (wid == 0) {
        asm volatile("tcgen05.relinquish_alloc_permit.cta_group::1.sync.aligned;");
        asm volatile("tcgen05.dealloc.cta_group::1.sync.aligned.b32 %0, %1;"
                     :: "r"(tmem), "r"(128u));
    }
#endif // TC_OK
}

// ============================================================
// Depthwise causal conv + bias + silu; writes fp32 xs AND bf16 hi/lo planes
// ============================================================
__global__ void conv_silu_kernel(const float* __restrict__ conv_w,
                                 const float* __restrict__ conv_b)
{
    int idx = blockIdx.x * blockDim.x + threadIdx.x;
    if (idx >= MROWS * INNER) return;
    int c = idx & (INNER - 1);
    int m = idx >> 11;
    int l = m & (LSEQ - 1);
    float w0 = conv_w[c * 4 + 0], w1 = conv_w[c * 4 + 1];
    float w2 = conv_w[c * 4 + 2], w3 = conv_w[c * 4 + 3];
    float s = conv_b[c];
    s = fmaf(w3, g_xr[(size_t)m * NIN + c], s);
    if (l >= 1) s = fmaf(w2, g_xr[(size_t)(m - 1) * NIN + c], s);
    if (l >= 2) s = fmaf(w1, g_xr[(size_t)(m - 2) * NIN + c], s);
    if (l >= 3) s = fmaf(w0, g_xr[(size_t)(m - 3) * NIN + c], s);
    float sig = 1.f / (1.f + __expf(-s));
    float v = s * sig;
    g_xs[idx] = v;
    __nv_bfloat16 vh = __float2bfloat16(v);
    __nv_bfloat16 vl = __float2bfloat16(v - __bfloat162float(vh));
    g_xsh[idx] = vh;
    g_xsl[idx] = vl;
}

// ============================================================
// dt2 = softplus(softplus(z)) = log(2 + exp(z))   (exact identity)
// ============================================================
__global__ __launch_bounds__(256) void dt_kernel(const float* __restrict__ W_dt,
                                                 const float* __restrict__ b_dt)
{
    __shared__ float Xs[64][65];
    __shared__ float Ws[64][65];
    int tid = threadIdx.x;
    int rb = blockIdx.y * 64, cb = blockIdx.x * 64;
    for (int e = tid; e < 64 * 64; e += 256) {
        int r = e >> 6, k = e & 63;
        Xs[r][k] = g_xdbl[(size_t)(rb + r) * XD + k];
        Ws[r][k] = W_dt[(size_t)(cb + r) * DTR + k];
    }
    __syncthreads();
    int tx = tid & 15, ty = tid >> 4;
    float acc[4][4];
#pragma unroll
    for (int i = 0; i < 4; i++)
#pragma unroll
        for (int j = 0; j < 4; j++) acc[i][j] = 0.f;
#pragma unroll 8
    for (int k = 0; k < 64; k++) {
        float a[4], b[4];
#pragma unroll
        for (int i = 0; i < 4; i++) { a[i] = Xs[ty * 4 + i][k]; b[i] = Ws[tx * 4 + i][k]; }
#pragma unroll
        for (int i = 0; i < 4; i++)
#pragma unroll
            for (int j = 0; j < 4; j++)
                acc[i][j] = fmaf(a[i], b[j], acc[i][j]);
    }
#pragma unroll
    for (int i = 0; i < 4; i++)
#pragma unroll
        for (int j = 0; j < 4; j++) {
            int r = rb + ty * 4 + i, d = cb + tx * 4 + j;
            float z = acc[i][j] + b_dt[d];
            // softplus(softplus(z)) == log(2 + e^z), computed stably
            float mz = fmaxf(z, 0.f);
            float v = mz + __logf(2.f * __expf(-mz) + __expf(z - mz));
            g_dt[(size_t)r * INNER + d] = v;
        }
}

// ============================================================
// Chunked selective scan; 32768 warps total (4096 blocks x 8 warps).
// w = b*16384 + c*1024 + dpair; each warp: 2 channels x 16 states.
// ============================================================
__global__ __launch_bounds__(256) void scanA_kernel(const float* __restrict__ A_log)
{
    int w = blockIdx.x * 8 + (threadIdx.x >> 5);    // 0..32767
    int lane = threadIdx.x & 31;
    int dpair = w & 1023;
    int c = (w >> 10) & 15;
    int b = w >> 14;
    int d = dpair * 2 + ((lane >> 4) & 1);
    int n = lane & 15;

    float a = -__expf(A_log[d * DST + n]);
    float h = 0.f, dts = 0.f;
    size_t m0 = (size_t)b * LSEQ + c * CLEN;
    for (int tt = 0; tt < CLEN; tt++) {
        size_t m = m0 + tt;
        float dt = g_dt[m * INNER + d];
        float xv = g_xs[m * INNER + d];
        float Bn = g_xdbl[m * XD + DTR + n];
        h = fmaf(__expf(dt * a), h, dt * Bn * xv);
        dts += dt;
    }
    size_t slot = (size_t)(b * NCHK + c) * INNER + d;
    g_hc[slot * DST + n] = h;
    if (n == 0) g_dts[slot] = dts;
}

__global__ __launch_bounds__(256) void scanB_kernel(const float* __restrict__ A_log)
{
    int idx = blockIdx.x * 256 + threadIdx.x;       // 0..65535
    int n = idx & 15;
    int d = (idx >> 4) & (INNER - 1);
    int b = idx >> 15;
    float a = -__expf(A_log[d * DST + n]);
    float s = 0.f;
#pragma unroll
    for (int c = 0; c < NCHK; c++) {
        size_t slot = (size_t)(b * NCHK + c) * INNER + d;
        g_hi[slot * DST + n] = s;
        s = fmaf(__expf(a * g_dts[slot]), s, g_hc[slot * DST + n]);
    }
}

__global__ __launch_bounds__(256) void scanC_kernel(const float* __restrict__ A_log,
                                                    const float* __restrict__ D_par)
{
    int w = blockIdx.x * 8 + (threadIdx.x >> 5);    // 0..32767
    int lane = threadIdx.x & 31;
    int dpair = w & 1023;
    int c = (w >> 10) & 15;
    int b = w >> 14;
    int d = dpair * 2 + ((lane >> 4) & 1);
    int n = lane & 15;

    float a = -__expf(A_log[d * DST + n]);
    float Dv = D_par[d];
    size_t slot = (size_t)(b * NCHK + c) * INNER + d;
    float h = g_hi[slot * DST + n];

    size_t m0 = (size_t)b * LSEQ + c * CLEN;
    for (int tt = 0; tt < CLEN; tt++) {
        size_t m = m0 + tt;
        float dt = g_dt[m * INNER + d];
        float xv = g_xs[m * INNER + d];
        float Bn = g_xdbl[m * XD + DTR + n];
        float Cn = g_xdbl[m * XD + DTR + DST + n];
        h = fmaf(__expf(dt * a), h, dt * Bn * xv);
        float pv = h * Cn;
        pv += __shfl_xor_sync(0xffffffffu, pv, 8);
        pv += __shfl_xor_sync(0xffffffffu, pv, 4);
        pv += __shfl_xor_sync(0xffffffffu, pv, 2);
        pv += __shfl_xor_sync(0xffffffffu, pv, 1);
        if (n == 0) {
            float resv = g_xr[m * NIN + INNER + d];
            float silu_r = resv / (1.f + __expf(-resv));
            float v = (pv + xv * Dv) * silu_r;
            __nv_bfloat16 vh = __float2bfloat16(v);
            __nv_bfloat16 vl = __float2bfloat16(v - __bfloat162float(vh));
            g_yh[m * INNER + d] = vh;
            g_yl[m * INNER + d] = vl;
        }
    }
}

// ============================================================
extern "C" void kernel_launch(void* const* d_in, const int* in_sizes, int n_in,
                              void* d_out, int out_size)
{
    const float* x      = (const float*)d_in[0];
    const float* W_in   = (const float*)d_in[1];
    const float* conv_w = (const float*)d_in[2];
    const float* conv_b = (const float*)d_in[3];
    const float* W_x    = (const float*)d_in[4];
    const float* W_dt   = (const float*)d_in[5];
    const float* b_dt   = (const float*)d_in[6];
    const float* A_log  = (const float*)d_in[7];
    const float* D_par  = (const float*)d_in[8];
    const float* W_out  = (const float*)d_in[9];
    float* out = (float*)d_out;

    float *xr_p, *xdbl_p;
    __nv_bfloat16 *xh_p, *xl_p, *wih_p, *wil_p, *woh_p, *wol_p, *yh_p, *yl_p;
    __nv_bfloat16 *xsh_p, *xsl_p, *wxh_p, *wxl_p;
    cudaGetSymbolAddress((void**)&xr_p,   g_xr);
    cudaGetSymbolAddress((void**)&xdbl_p, g_xdbl);
    cudaGetSymbolAddress((void**)&xh_p,   g_xh);
    cudaGetSymbolAddress((void**)&xl_p,   g_xl);
    cudaGetSymbolAddress((void**)&wih_p,  g_wih);
    cudaGetSymbolAddress((void**)&wil_p,  g_wil);
    cudaGetSymbolAddress((void**)&woh_p,  g_woh);
    cudaGetSymbolAddress((void**)&wol_p,  g_wol);
    cudaGetSymbolAddress((void**)&yh_p,   g_yh);
    cudaGetSymbolAddress((void**)&yl_p,   g_yl);
    cudaGetSymbolAddress((void**)&xsh_p,  g_xsh);
    cudaGetSymbolAddress((void**)&xsl_p,  g_xsl);
    cudaGetSymbolAddress((void**)&wxh_p,  g_wxh);
    cudaGetSymbolAddress((void**)&wxl_p,  g_wxl);

    cudaFuncSetAttribute(tc_gemm_split,
                         cudaFuncAttributeMaxDynamicSharedMemorySize, TC_SMEM_BYTES);

    // 0) one-time bf16 hi/lo splits
    {
        int n4 = (MROWS * DMODEL) / 4;
        split_bf16_kernel<<<(n4 + 255) / 256, 256>>>(
            (const float4*)x, (__nv_bfloat162*)xh_p, (__nv_bfloat162*)xl_p, n4);
        n4 = (NIN * DMODEL) / 4;
        split_bf16_kernel<<<(n4 + 255) / 256, 256>>>(
            (const float4*)W_in, (__nv_bfloat162*)wih_p, (__nv_bfloat162*)wil_p, n4);
        n4 = (DMODEL * INNER) / 4;
        split_bf16_kernel<<<(n4 + 255) / 256, 256>>>(
            (const float4*)W_out, (__nv_bfloat162*)woh_p, (__nv_bfloat162*)wol_p, n4);
        n4 = (XD * INNER) / 4;   // W_x: 96 x 2048
        split_bf16_kernel<<<(n4 + 255) / 256, 256>>>(
            (const float4*)W_x, (__nv_bfloat162*)wxh_p, (__nv_bfloat162*)wxl_p, n4);
        pad_wx_kernel<<<(32 * INNER + 255) / 256, 256>>>();
    }

    // 1) xr = x @ W_in^T
    tc_gemm_split<<<dim3(NIN / TC_BN, MROWS / TC_BM), 256, TC_SMEM_BYTES>>>(
        xh_p, xl_p, wih_p, wil_p, xr_p, MROWS, NIN, DMODEL, NIN, NIN);

    // 2) depthwise causal conv + silu -> g_xs + hi/lo planes
    conv_silu_kernel<<<(MROWS * INNER + 255) / 256, 256>>>(conv_w, conv_b);

    // 3) x_dbl = xs @ W_x^T  (tcgen05, N padded to 128, write 96 cols)
    tc_gemm_split<<<dim3(1, MROWS / TC_BM), 256, TC_SMEM_BYTES>>>(
        xsh_p, xsl_p, wxh_p, wxl_p, xdbl_p, MROWS, 128, INNER, XD, XD);

    // 4) dt2 = log(2 + exp(x_dbl[:,:64] @ W_dt^T + b_dt))
    dt_kernel<<<dim3(INNER / 64, MROWS / 64), 256>>>(W_dt, b_dt);

    // 5) chunked selective scan (32768 warps for A/C: b x chunk x dpair)
    scanA_kernel<<<4096, 256>>>(A_log);
    scanB_kernel<<<256, 256>>>(A_log);
    scanC_kernel<<<4096, 256>>>(A_log, D_par);

    // 6) out = y @ W_out^T
    tc_gemm_split<<<dim3(DMODEL / TC_BN, MROWS / TC_BM), 256, TC_SMEM_BYTES>>>(
        yh_p, yl_p, woh_p, wol_p, out, MROWS, DMODEL, INNER, DMODEL, DMODEL);
}

// round 13
// speedup vs baseline: 6.6199x; 1.0599x over previous
#include <cuda_runtime.h>
#include <cuda_bf16.h>
#include <math.h>
#include <stdint.h>

#define BSZ    2
#define LSEQ   2048
#define DMODEL 1024
#define INNER  2048
#define MROWS  4096      // BSZ*LSEQ
#define NIN    4096      // 2*INNER
#define DTR    64
#define DST    16
#define XD     96        // DTR + 2*DST
#define NCHK   16        // scan chunks
#define CLEN   128       // LSEQ / NCHK
#define KSLC   4         // x_dbl split-K slices

#if defined(__CUDA_ARCH_FEAT_SM103_ALL) || defined(__CUDA_ARCH_FEAT_SM100_ALL)
#define TC_OK 1
#else
#define TC_OK 0
#endif

// ---- scratch (device globals; no allocation allowed) ----
__device__ float g_xr[(size_t)MROWS * NIN];     // x @ W_in^T  (xs | res)
__device__ float g_xs[(size_t)MROWS * INNER];   // conv+silu output (fp32)
__device__ float g_xdbl[(size_t)MROWS * XD];    // xs @ W_x^T (reduced)
__device__ float g_xdp[(size_t)KSLC * MROWS * XD];  // split-K partials
__device__ float g_dt[(size_t)MROWS * INNER];   // dt2
// chunked-scan intermediates
__device__ float g_hc[(size_t)BSZ * NCHK * INNER * DST];
__device__ float g_hi[(size_t)BSZ * NCHK * INNER * DST];
__device__ float g_dts[(size_t)BSZ * NCHK * INNER];
// bf16 hi/lo split planes
__device__ __align__(16) __nv_bfloat16 g_xh[(size_t)MROWS * DMODEL];
__device__ __align__(16) __nv_bfloat16 g_xl[(size_t)MROWS * DMODEL];
__device__ __align__(16) __nv_bfloat16 g_wih[(size_t)NIN * DMODEL];
__device__ __align__(16) __nv_bfloat16 g_wil[(size_t)NIN * DMODEL];
__device__ __align__(16) __nv_bfloat16 g_woh[(size_t)DMODEL * INNER];
__device__ __align__(16) __nv_bfloat16 g_wol[(size_t)DMODEL * INNER];
__device__ __align__(16) __nv_bfloat16 g_yh[(size_t)MROWS * INNER];
__device__ __align__(16) __nv_bfloat16 g_yl[(size_t)MROWS * INNER];
__device__ __align__(16) __nv_bfloat16 g_xsh[(size_t)MROWS * INNER];
__device__ __align__(16) __nv_bfloat16 g_xsl[(size_t)MROWS * INNER];
__device__ __align__(16) __nv_bfloat16 g_wxh[(size_t)128 * INNER];   // W_x padded 96->128
__device__ __align__(16) __nv_bfloat16 g_wxl[(size_t)128 * INNER];
__device__ __align__(16) __nv_bfloat16 g_dbh[(size_t)MROWS * DTR];   // xdbl[:, :64] hi
__device__ __align__(16) __nv_bfloat16 g_dbl[(size_t)MROWS * DTR];   // xdbl[:, :64] lo
__device__ __align__(16) __nv_bfloat16 g_wdh[(size_t)INNER * DTR];   // W_dt hi
__device__ __align__(16) __nv_bfloat16 g_wdl[(size_t)INNER * DTR];   // W_dt lo

// ============================================================
// fp32 -> bf16 hi/lo split planes
// ============================================================
__global__ void split_bf16_kernel(const float4* __restrict__ src,
                                  __nv_bfloat162* __restrict__ hi,
                                  __nv_bfloat162* __restrict__ lo, int n4)
{
    int i = blockIdx.x * blockDim.x + threadIdx.x;
    if (i >= n4) return;
    float4 f = src[i];
    __nv_bfloat16 hx = __float2bfloat16(f.x), hy = __float2bfloat16(f.y);
    __nv_bfloat16 hz = __float2bfloat16(f.z), hw = __float2bfloat16(f.w);
    __nv_bfloat16 lx = __float2bfloat16(f.x - __bfloat162float(hx));
    __nv_bfloat16 ly = __float2bfloat16(f.y - __bfloat162float(hy));
    __nv_bfloat16 lz = __float2bfloat16(f.z - __bfloat162float(hz));
    __nv_bfloat16 lw = __float2bfloat16(f.w - __bfloat162float(hw));
    hi[i * 2 + 0] = __halves2bfloat162(hx, hy);
    hi[i * 2 + 1] = __halves2bfloat162(hz, hw);
    lo[i * 2 + 0] = __halves2bfloat162(lx, ly);
    lo[i * 2 + 1] = __halves2bfloat162(lz, lw);
}

// zero the pad rows (96..127) of the W_x planes
__global__ void pad_wx_kernel()
{
    int i = blockIdx.x * blockDim.x + threadIdx.x;
    if (i >= 32 * INNER) return;
    size_t o = (size_t)96 * INNER + i;
    g_wxh[o] = __float2bfloat16(0.f);
    g_wxl[o] = __float2bfloat16(0.f);
}

// sum x_dbl split-K partials -> g_xdbl; also emit bf16 planes of cols 0..63
__global__ void reduce_xdbl_kernel()
{
    int i = blockIdx.x * blockDim.x + threadIdx.x;
    if (i >= MROWS * XD) return;
    float s = g_xdp[i] + g_xdp[(size_t)MROWS * XD + i]
            + g_xdp[2 * (size_t)MROWS * XD + i] + g_xdp[3 * (size_t)MROWS * XD + i];
    g_xdbl[i] = s;
    int col = i % XD;
    if (col < DTR) {
        int m = i / XD;
        __nv_bfloat16 vh = __float2bfloat16(s);
        __nv_bfloat16 vl = __float2bfloat16(s - __bfloat162float(vh));
        g_dbh[(size_t)m * DTR + col] = vh;
        g_dbl[(size_t)m * DTR + col] = vl;
    }
}

// ============================================================
// tcgen05 split-GEMM core helpers
// ============================================================
#define TC_BM 128
#define TC_BN 128
#define TC_BK 64
#define TC_TILE_BYTES 16384
#define TC_STAGE_BYTES (4 * TC_TILE_BYTES)
#define TC_SMEM_BYTES (1024 + 2 * TC_STAGE_BYTES)
#define TC_DT_SMEM (1024 + 4 * TC_TILE_BYTES)
#define TC_IDESC 0x8200490u

__device__ __forceinline__ uint32_t smem_u32(const void* p) {
    uint32_t a;
    asm("{ .reg .u64 t; cvta.to.shared.u64 t, %1; cvt.u32.u64 %0, t; }"
        : "=r"(a) : "l"(p));
    return a;
}

#if TC_OK
__device__ __forceinline__ uint64_t make_sw128_desc(uint32_t addr) {
    return ( (uint64_t)2 << 61 ) | ( (uint64_t)1 << 46 )
         | ( (uint64_t)64 << 32 ) | ( (uint64_t)1 << 16 )
         | ( (uint64_t)(addr >> 4) & 0x3FFF );
}

__device__ __forceinline__ void mma_ss_bf16(uint32_t d, uint64_t ad, uint64_t bd,
                                            uint32_t acc) {
    asm volatile(
        "{\n\t.reg .pred p;\n\t"
        "setp.ne.u32 p, %4, 0;\n\t"
        "tcgen05.mma.cta_group::1.kind::f16 [%0], %1, %2, %3, {%5, %5, %5, %5}, p;\n\t}"
        :: "r"(d), "l"(ad), "l"(bd), "r"(TC_IDESC), "r"(acc), "r"(0u)
        : "memory");
}

__device__ __forceinline__ void mbar_wait_parity(uint32_t mbar, uint32_t parity) {
    asm volatile(
        "{\n\t.reg .pred P;\n\t"
        "WL_%=:\n\t"
        "mbarrier.try_wait.parity.acquire.cta.shared::cta.b64 P, [%0], %1, 0x989680;\n\t"
        "@!P bra WL_%=;\n\t}"
        :: "r"(mbar), "r"(parity) : "memory");
}

__device__ __forceinline__ void tmem_ld32(uint32_t* r, uint32_t addr) {
    asm volatile(
        "tcgen05.ld.sync.aligned.32x32b.x32.b32 "
        "{%0, %1, %2, %3, %4, %5, %6, %7, "
        " %8, %9, %10, %11, %12, %13, %14, %15, "
        " %16, %17, %18, %19, %20, %21, %22, %23, "
        " %24, %25, %26, %27, %28, %29, %30, %31}, [%32];"
        : "=r"(r[0]), "=r"(r[1]), "=r"(r[2]), "=r"(r[3]),
          "=r"(r[4]), "=r"(r[5]), "=r"(r[6]), "=r"(r[7]),
          "=r"(r[8]), "=r"(r[9]), "=r"(r[10]), "=r"(r[11]),
          "=r"(r[12]), "=r"(r[13]), "=r"(r[14]), "=r"(r[15]),
          "=r"(r[16]), "=r"(r[17]), "=r"(r[18]), "=r"(r[19]),
          "=r"(r[20]), "=r"(r[21]), "=r"(r[22]), "=r"(r[23]),
          "=r"(r[24]), "=r"(r[25]), "=r"(r[26]), "=r"(r[27]),
          "=r"(r[28]), "=r"(r[29]), "=r"(r[30]), "=r"(r[31])
        : "r"(addr));
}

__device__ __forceinline__ void copy_tile(const __nv_bfloat16* __restrict__ plane,
                                          int row0, int k0, int ld,
                                          uint32_t dst, int tid)
{
#pragma unroll
    for (int p = 0; p < 4; p++) {
        int idx = p * 256 + tid;
        int r = idx >> 3;
        int b = (idx & 7) << 4;
        uint32_t off = (uint32_t)(r * 128 + b);
        uint32_t swz = off ^ ((off >> 3) & 0x70);
        const void* src = plane + (size_t)(row0 + r) * ld + k0 + (b >> 1);
        asm volatile("cp.async.cg.shared.global [%0], [%1], 16;"
                     :: "r"(dst + swz), "l"(src) : "memory");
    }
}
#endif // TC_OK

// ============================================================
// General pipelined split-GEMM. gridDim.z = split-K slices.
// C[M, ncols](+z offset) = A[:, z*Kz : z*Kz+Kloop] * B^T slice.
// ============================================================
__global__ __launch_bounds__(256) void tc_gemm_split(
    const __nv_bfloat16* __restrict__ Ah, const __nv_bfloat16* __restrict__ Al,
    const __nv_bfloat16* __restrict__ Bh, const __nv_bfloat16* __restrict__ Bl,
    float* __restrict__ C, int ldA, int ldB, int Kloop, int ldC, int ncols,
    int Kz, size_t Cz)
{
#if TC_OK
    extern __shared__ char smem[];
    const uint32_t sb = smem_u32(smem);
    const uint32_t MBAR0 = sb + 8;
    const uint32_t MBAR1 = sb + 16;
    const uint32_t DONE  = sb + 24;
    const uint32_t S_DATA = sb + 1024;

    const int tid = threadIdx.x;
    const int wid = tid >> 5, lid = tid & 31;
    const int bm = blockIdx.y * TC_BM;
    const int bn = blockIdx.x * TC_BN;
    const int koff = blockIdx.z * Kz;
    C += (size_t)blockIdx.z * Cz;

    if (wid == 0) {
        asm volatile(
            "tcgen05.alloc.cta_group::1.sync.aligned.shared::cta.b32 [%0], %1;"
            :: "r"(sb), "r"(128u) : "memory");
    }
    if (tid == 0) {
        asm volatile("mbarrier.init.shared.b64 [%0], 1;" :: "r"(MBAR0) : "memory");
        asm volatile("mbarrier.init.shared.b64 [%0], 1;" :: "r"(MBAR1) : "memory");
        asm volatile("mbarrier.init.shared.b64 [%0], 1;" :: "r"(DONE)  : "memory");
    }
    __syncthreads();
    uint32_t tmem;
    asm volatile("ld.shared.b32 %0, [%1];" : "=r"(tmem) : "r"(sb));

    const int nch = Kloop / TC_BK;

    {
        uint32_t st = S_DATA;
        copy_tile(Ah, bm, koff, ldA, st + 0 * TC_TILE_BYTES, tid);
        copy_tile(Al, bm, koff, ldA, st + 1 * TC_TILE_BYTES, tid);
        copy_tile(Bh, bn, koff, ldB, st + 2 * TC_TILE_BYTES, tid);
        copy_tile(Bl, bn, koff, ldB, st + 3 * TC_TILE_BYTES, tid);
        asm volatile("cp.async.commit_group;" ::: "memory");
    }

    for (int ch = 0; ch < nch; ch++) {
        const int s = ch & 1;
        if (ch + 1 < nch) {
            const int nx = ch + 1, t = nx & 1;
            if (nx >= 2) {
                uint32_t py = (uint32_t)(((nx - 2 - t) >> 1) & 1);
                mbar_wait_parity(t ? MBAR1 : MBAR0, py);
            }
            const int k0 = koff + nx * TC_BK;
            uint32_t st = S_DATA + (uint32_t)t * TC_STAGE_BYTES;
            copy_tile(Ah, bm, k0, ldA, st + 0 * TC_TILE_BYTES, tid);
            copy_tile(Al, bm, k0, ldA, st + 1 * TC_TILE_BYTES, tid);
            copy_tile(Bh, bn, k0, ldB, st + 2 * TC_TILE_BYTES, tid);
            copy_tile(Bl, bn, k0, ldB, st + 3 * TC_TILE_BYTES, tid);
            asm volatile("cp.async.commit_group;" ::: "memory");
            asm volatile("cp.async.wait_group 1;" ::: "memory");
        } else {
            asm volatile("cp.async.wait_group 0;" ::: "memory");
        }
        asm volatile("fence.proxy.async.shared::cta;" ::: "memory");
        __syncthreads();

        if (tid == 0) {
            uint32_t base = S_DATA + (uint32_t)s * TC_STAGE_BYTES;
            uint64_t adh = make_sw128_desc(base);
            uint64_t adl = make_sw128_desc(base + 1 * TC_TILE_BYTES);
            uint64_t bdh = make_sw128_desc(base + 2 * TC_TILE_BYTES);
            uint64_t bdl = make_sw128_desc(base + 3 * TC_TILE_BYTES);
#pragma unroll
            for (int ks = 0; ks < 4; ks++) {
                mma_ss_bf16(tmem, adh + ks * 2, bdh + ks * 2,
                            (uint32_t)(ch != 0 || ks != 0));
                mma_ss_bf16(tmem, adl + ks * 2, bdh + ks * 2, 1u);
                mma_ss_bf16(tmem, adh + ks * 2, bdl + ks * 2, 1u);
            }
            asm volatile(
                "tcgen05.commit.cta_group::1.mbarrier::arrive::one.shared::cluster.b64 [%0];"
                :: "r"(s ? MBAR1 : MBAR0) : "memory");
        }
    }

    if (tid == 0) {
        asm volatile(
            "tcgen05.commit.cta_group::1.mbarrier::arrive::one.shared::cluster.b64 [%0];"
            :: "r"(DONE) : "memory");
    }
    mbar_wait_parity(DONE, 0);
    asm volatile("tcgen05.fence::after_thread_sync;" ::: "memory");

    if (wid < 4) {
        int m = bm + wid * 32 + lid;
        float* cp = C + (size_t)m * ldC + bn;
#pragma unroll
        for (int base = 0; base < 128; base += 32) {
            if (bn + base >= ncols) break;
            uint32_t r[32];
            tmem_ld32(r, tmem + base);
            asm volatile("tcgen05.wait::ld.sync.aligned;" ::: "memory");
#pragma unroll
            for (int j = 0; j < 32; j += 4) {
                if (bn + base + j < ncols) {
                    float4 v = make_float4(__uint_as_float(r[j]), __uint_as_float(r[j + 1]),
                                           __uint_as_float(r[j + 2]), __uint_as_float(r[j + 3]));
                    *(float4*)(cp + base + j) = v;
                }
            }
        }
    }
    __syncthreads();
    if (tid == 0) {
        asm volatile("mbarrier.inval.shared.b64 [%0];" :: "r"(MBAR0) : "memory");
        asm volatile("mbarrier.inval.shared.b64 [%0];" :: "r"(MBAR1) : "memory");
        asm volatile("mbarrier.inval.shared.b64 [%0];" :: "r"(DONE)  : "memory");
    }
    __syncthreads();
    if (wid == 0) {
        asm volatile("tcgen05.relinquish_alloc_permit.cta_group::1.sync.aligned;");
        asm volatile("tcgen05.dealloc.cta_group::1.sync.aligned.b32 %0, %1;"
                     :: "r"(tmem), "r"(128u));
    }
#endif // TC_OK
}

// ============================================================
// dt GEMM on tcgen05: K=64 single chunk, epilogue = +b_dt then
// softplus(softplus(z)) = log(2 + e^z).
// A = g_dbh/g_dbl [M,64], B = g_wdh/g_wdl [2048,64].
// ============================================================
__global__ __launch_bounds__(256) void tc_dt_gemm(const float* __restrict__ b_dt)
{
#if TC_OK
    extern __shared__ char smem[];
    const uint32_t sb = smem_u32(smem);
    const uint32_t MBAR = sb + 8;
    const uint32_t S_AH = sb + 1024;
    const uint32_t S_AL = S_AH + TC_TILE_BYTES;
    const uint32_t S_BH = S_AL + TC_TILE_BYTES;
    const uint32_t S_BL = S_BH + TC_TILE_BYTES;

    const int tid = threadIdx.x;
    const int wid = tid >> 5, lid = tid & 31;
    const int bm = blockIdx.y * TC_BM;
    const int bn = blockIdx.x * TC_BN;

    if (wid == 0) {
        asm volatile(
            "tcgen05.alloc.cta_group::1.sync.aligned.shared::cta.b32 [%0], %1;"
            :: "r"(sb), "r"(128u) : "memory");
    }
    if (tid == 0)
        asm volatile("mbarrier.init.shared.b64 [%0], 1;" :: "r"(MBAR) : "memory");
    __syncthreads();
    uint32_t tmem;
    asm volatile("ld.shared.b32 %0, [%1];" : "=r"(tmem) : "r"(sb));

    copy_tile(g_dbh, bm, 0, DTR, S_AH, tid);
    copy_tile(g_dbl, bm, 0, DTR, S_AL, tid);
    copy_tile(g_wdh, bn, 0, DTR, S_BH, tid);
    copy_tile(g_wdl, bn, 0, DTR, S_BL, tid);
    asm volatile("cp.async.commit_group;" ::: "memory");
    asm volatile("cp.async.wait_group 0;" ::: "memory");
    asm volatile("fence.proxy.async.shared::cta;" ::: "memory");
    __syncthreads();

    if (tid == 0) {
        uint64_t adh = make_sw128_desc(S_AH), adl = make_sw128_desc(S_AL);
        uint64_t bdh = make_sw128_desc(S_BH), bdl = make_sw128_desc(S_BL);
#pragma unroll
        for (int ks = 0; ks < 4; ks++) {
            mma_ss_bf16(tmem, adh + ks * 2, bdh + ks * 2, (uint32_t)(ks != 0));
            mma_ss_bf16(tmem, adl + ks * 2, bdh + ks * 2, 1u);
            mma_ss_bf16(tmem, adh + ks * 2, bdl + ks * 2, 1u);
        }
        asm volatile(
            "tcgen05.commit.cta_group::1.mbarrier::arrive::one.shared::cluster.b64 [%0];"
            :: "r"(MBAR) : "memory");
    }
    mbar_wait_parity(MBAR, 0);
    asm volatile("tcgen05.fence::after_thread_sync;" ::: "memory");

    if (wid < 4) {
        int m = bm + wid * 32 + lid;
        float* cp = g_dt + (size_t)m * INNER + bn;
#pragma unroll
        for (int base = 0; base < 128; base += 32) {
            uint32_t r[32];
            tmem_ld32(r, tmem + base);
            asm volatile("tcgen05.wait::ld.sync.aligned;" ::: "memory");
#pragma unroll
            for (int j = 0; j < 32; j++) {
                float z = __uint_as_float(r[j]) + b_dt[bn + base + j];
                float mz = fmaxf(z, 0.f);
                cp[base + j] = mz + __logf(2.f * __expf(-mz) + __expf(z - mz));
            }
        }
    }
    __syncthreads();
    if (tid == 0)
        asm volatile("mbarrier.inval.shared.b64 [%0];" :: "r"(MBAR) : "memory");
    __syncthreads();
    if (wid == 0) {
        asm volatile("tcgen05.relinquish_alloc_permit.cta_group::1.sync.aligned;");
        asm volatile("tcgen05.dealloc.cta_group::1.sync.aligned.b32 %0, %1;"
                     :: "r"(tmem), "r"(128u));
    }
#endif // TC_OK
}

// ============================================================
// Depthwise causal conv + bias + silu; writes fp32 xs AND bf16 hi/lo planes
// ============================================================
__global__ void conv_silu_kernel(const float* __restrict__ conv_w,
                                 const float* __restrict__ conv_b)
{
    int idx = blockIdx.x * blockDim.x + threadIdx.x;
    if (idx >= MROWS * INNER) return;
    int c = idx & (INNER - 1);
    int m = idx >> 11;
    int l = m & (LSEQ - 1);
    float w0 = conv_w[c * 4 + 0], w1 = conv_w[c * 4 + 1];
    float w2 = conv_w[c * 4 + 2], w3 = conv_w[c * 4 + 3];
    float s = conv_b[c];
    s = fmaf(w3, g_xr[(size_t)m * NIN + c], s);
    if (l >= 1) s = fmaf(w2, g_xr[(size_t)(m - 1) * NIN + c], s);
    if (l >= 2) s = fmaf(w1, g_xr[(size_t)(m - 2) * NIN + c], s);
    if (l >= 3) s = fmaf(w0, g_xr[(size_t)(m - 3) * NIN + c], s);
    float sig = 1.f / (1.f + __expf(-s));
    float v = s * sig;
    g_xs[idx] = v;
    __nv_bfloat16 vh = __float2bfloat16(v);
    __nv_bfloat16 vl = __float2bfloat16(v - __bfloat162float(vh));
    g_xsh[idx] = vh;
    g_xsl[idx] = vl;
}

// ============================================================
// Chunked selective scan (unchanged from R12)
// ============================================================
__global__ __launch_bounds__(256) void scanA_kernel(const float* __restrict__ A_log)
{
    int w = blockIdx.x * 8 + (threadIdx.x >> 5);
    int lane = threadIdx.x & 31;
    int dpair = w & 1023;
    int c = (w >> 10) & 15;
    int b = w >> 14;
    int d = dpair * 2 + ((lane >> 4) & 1);
    int n = lane & 15;

    float a = -__expf(A_log[d * DST + n]);
    float h = 0.f, dts = 0.f;
    size_t m0 = (size_t)b * LSEQ + c * CLEN;
    for (int tt = 0; tt < CLEN; tt++) {
        size_t m = m0 + tt;
        float dt = g_dt[m * INNER + d];
        float xv = g_xs[m * INNER + d];
        float Bn = g_xdbl[m * XD + DTR + n];
        h = fmaf(__expf(dt * a), h, dt * Bn * xv);
        dts += dt;
    }
    size_t slot = (size_t)(b * NCHK + c) * INNER + d;
    g_hc[slot * DST + n] = h;
    if (n == 0) g_dts[slot] = dts;
}

__global__ __launch_bounds__(256) void scanB_kernel(const float* __restrict__ A_log)
{
    int idx = blockIdx.x * 256 + threadIdx.x;
    int n = idx & 15;
    int d = (idx >> 4) & (INNER - 1);
    int b = idx >> 15;
    float a = -__expf(A_log[d * DST + n]);
    float s = 0.f;
#pragma unroll
    for (int c = 0; c < NCHK; c++) {
        size_t slot = (size_t)(b * NCHK + c) * INNER + d;
        g_hi[slot * DST + n] = s;
        s = fmaf(__expf(a * g_dts[slot]), s, g_hc[slot * DST + n]);
    }
}

__global__ __launch_bounds__(256) void scanC_kernel(const float* __restrict__ A_log,
                                                    const float* __restrict__ D_par)
{
    int w = blockIdx.x * 8 + (threadIdx.x >> 5);
    int lane = threadIdx.x & 31;
    int dpair = w & 1023;
    int c = (w >> 10) & 15;
    int b = w >> 14;
    int d = dpair * 2 + ((lane >> 4) & 1);
    int n = lane & 15;

    float a = -__expf(A_log[d * DST + n]);
    float Dv = D_par[d];
    size_t slot = (size_t)(b * NCHK + c) * INNER + d;
    float h = g_hi[slot * DST + n];

    size_t m0 = (size_t)b * LSEQ + c * CLEN;
    for (int tt = 0; tt < CLEN; tt++) {
        size_t m = m0 + tt;
        float dt = g_dt[m * INNER + d];
        float xv = g_xs[m * INNER + d];
        float Bn = g_xdbl[m * XD + DTR + n];
        float Cn = g_xdbl[m * XD + DTR + DST + n];
        h = fmaf(__expf(dt * a), h, dt * Bn * xv);
        float pv = h * Cn;
        pv += __shfl_xor_sync(0xffffffffu, pv, 8);
        pv += __shfl_xor_sync(0xffffffffu, pv, 4);
        pv += __shfl_xor_sync(0xffffffffu, pv, 2);
        pv += __shfl_xor_sync(0xffffffffu, pv, 1);
        if (n == 0) {
            float resv = g_xr[m * NIN + INNER + d];
            float silu_r = resv / (1.f + __expf(-resv));
            float v = (pv + xv * Dv) * silu_r;
            __nv_bfloat16 vh = __float2bfloat16(v);
            __nv_bfloat16 vl = __float2bfloat16(v - __bfloat162float(vh));
            g_yh[m * INNER + d] = vh;
            g_yl[m * INNER + d] = vl;
        }
    }
}

// ============================================================
extern "C" void kernel_launch(void* const* d_in, const int* in_sizes, int n_in,
                              void* d_out, int out_size)
{
    const float* x      = (const float*)d_in[0];
    const float* W_in   = (const float*)d_in[1];
    const float* conv_w = (const float*)d_in[2];
    const float* conv_b = (const float*)d_in[3];
    const float* W_x    = (const float*)d_in[4];
    const float* W_dt   = (const float*)d_in[5];
    const float* b_dt   = (const float*)d_in[6];
    const float* A_log  = (const float*)d_in[7];
    const float* D_par  = (const float*)d_in[8];
    const float* W_out  = (const float*)d_in[9];
    float* out = (float*)d_out;

    float *xr_p, *xdp_p;
    __nv_bfloat16 *xh_p, *xl_p, *wih_p, *wil_p, *woh_p, *wol_p, *yh_p, *yl_p;
    __nv_bfloat16 *xsh_p, *xsl_p, *wxh_p, *wxl_p, *wdh_p, *wdl_p;
    cudaGetSymbolAddress((void**)&xr_p,   g_xr);
    cudaGetSymbolAddress((void**)&xdp_p,  g_xdp);
    cudaGetSymbolAddress((void**)&xh_p,   g_xh);
    cudaGetSymbolAddress((void**)&xl_p,   g_xl);
    cudaGetSymbolAddress((void**)&wih_p,  g_wih);
    cudaGetSymbolAddress((void**)&wil_p,  g_wil);
    cudaGetSymbolAddress((void**)&woh_p,  g_woh);
    cudaGetSymbolAddress((void**)&wol_p,  g_wol);
    cudaGetSymbolAddress((void**)&yh_p,   g_yh);
    cudaGetSymbolAddress((void**)&yl_p,   g_yl);
    cudaGetSymbolAddress((void**)&xsh_p,  g_xsh);
    cudaGetSymbolAddress((void**)&xsl_p,  g_xsl);
    cudaGetSymbolAddress((void**)&wxh_p,  g_wxh);
    cudaGetSymbolAddress((void**)&wxl_p,  g_wxl);
    cudaGetSymbolAddress((void**)&wdh_p,  g_wdh);
    cudaGetSymbolAddress((void**)&wdl_p,  g_wdl);

    cudaFuncSetAttribute(tc_gemm_split,
                         cudaFuncAttributeMaxDynamicSharedMemorySize, TC_SMEM_BYTES);
    cudaFuncSetAttribute(tc_dt_gemm,
                         cudaFuncAttributeMaxDynamicSharedMemorySize, TC_DT_SMEM);

    // 0) one-time bf16 hi/lo splits
    {
        int n4 = (MROWS * DMODEL) / 4;
        split_bf16_kernel<<<(n4 + 255) / 256, 256>>>(
            (const float4*)x, (__nv_bfloat162*)xh_p, (__nv_bfloat162*)xl_p, n4);
        n4 = (NIN * DMODEL) / 4;
        split_bf16_kernel<<<(n4 + 255) / 256, 256>>>(
            (const float4*)W_in, (__nv_bfloat162*)wih_p, (__nv_bfloat162*)wil_p, n4);
        n4 = (DMODEL * INNER) / 4;
        split_bf16_kernel<<<(n4 + 255) / 256, 256>>>(
            (const float4*)W_out, (__nv_bfloat162*)woh_p, (__nv_bfloat162*)wol_p, n4);
        n4 = (XD * INNER) / 4;
        split_bf16_kernel<<<(n4 + 255) / 256, 256>>>(
            (const float4*)W_x, (__nv_bfloat162*)wxh_p, (__nv_bfloat162*)wxl_p, n4);
        n4 = (INNER * DTR) / 4;
        split_bf16_kernel<<<(n4 + 255) / 256, 256>>>(
            (const float4*)W_dt, (__nv_bfloat162*)wdh_p, (__nv_bfloat162*)wdl_p, n4);
        pad_wx_kernel<<<(32 * INNER + 255) / 256, 256>>>();
    }

    // 1) xr = x @ W_in^T
    tc_gemm_split<<<dim3(NIN / TC_BN, MROWS / TC_BM, 1), 256, TC_SMEM_BYTES>>>(
        xh_p, xl_p, wih_p, wil_p, xr_p, DMODEL, DMODEL, DMODEL, NIN, NIN, 0, 0);

    // 2) depthwise causal conv + silu
    conv_silu_kernel<<<(MROWS * INNER + 255) / 256, 256>>>(conv_w, conv_b);

    // 3) x_dbl partials: split-K x4 (z = K slice), then reduce (+ dt-input planes)
    tc_gemm_split<<<dim3(1, MROWS / TC_BM, KSLC), 256, TC_SMEM_BYTES>>>(
        xsh_p, xsl_p, wxh_p, wxl_p, xdp_p, INNER, INNER, INNER / KSLC, XD, XD,
        INNER / KSLC, (size_t)MROWS * XD);
    reduce_xdbl_kernel<<<(MROWS * XD + 255) / 256, 256>>>();

    // 4) dt = log(2 + exp(xdbl[:,:64] @ W_dt^T + b_dt))  (tcgen05)
    tc_dt_gemm<<<dim3(INNER / TC_BN, MROWS / TC_BM), 256, TC_DT_SMEM>>>(b_dt);

    // 5) chunked selective scan
    scanA_kernel<<<4096, 256>>>(A_log);
    scanB_kernel<<<256, 256>>>(A_log);
    scanC_kernel<<<4096, 256>>>(A_log, D_par);

    // 6) out = y @ W_out^T
    tc_gemm_split<<<dim3(DMODEL / TC_BN, MROWS / TC_BM, 1), 256, TC_SMEM_BYTES>>>(
        yh_p, yl_p, woh_p, wol_p, out, INNER, INNER, INNER, DMODEL, DMODEL, 0, 0);
}

// round 14
// speedup vs baseline: 9.0250x; 1.3633x over previous
#include <cuda_runtime.h>
#include <cuda_bf16.h>
#include <math.h>
#include <stdint.h>

#define BSZ    2
#define LSEQ   2048
#define DMODEL 1024
#define INNER  2048
#define MROWS  4096      // BSZ*LSEQ
#define NIN    4096      // 2*INNER
#define DTR    64
#define DST    16
#define XD     96        // DTR + 2*DST
#define NCHK   32        // scan chunks
#define CLEN   64        // LSEQ / NCHK
#define KSLC   4         // x_dbl split-K slices

#if defined(__CUDA_ARCH_FEAT_SM103_ALL) || defined(__CUDA_ARCH_FEAT_SM100_ALL)
#define TC_OK 1
#else
#define TC_OK 0
#endif

// ---- scratch (device globals; no allocation allowed) ----
__device__ float g_xr[(size_t)MROWS * NIN];
__device__ float g_xs[(size_t)MROWS * INNER];
__device__ float g_xdbl[(size_t)MROWS * XD];
__device__ float g_xdp[(size_t)KSLC * MROWS * XD];
__device__ float g_dt[(size_t)MROWS * INNER];
__device__ float g_hc[(size_t)BSZ * NCHK * INNER * DST];
__device__ float g_hi[(size_t)BSZ * NCHK * INNER * DST];
__device__ float g_dts[(size_t)BSZ * NCHK * INNER];
__device__ __align__(16) __nv_bfloat16 g_xh[(size_t)MROWS * DMODEL];
__device__ __align__(16) __nv_bfloat16 g_xl[(size_t)MROWS * DMODEL];
__device__ __align__(16) __nv_bfloat16 g_wih[(size_t)NIN * DMODEL];
__device__ __align__(16) __nv_bfloat16 g_wil[(size_t)NIN * DMODEL];
__device__ __align__(16) __nv_bfloat16 g_woh[(size_t)DMODEL * INNER];
__device__ __align__(16) __nv_bfloat16 g_wol[(size_t)DMODEL * INNER];
__device__ __align__(16) __nv_bfloat16 g_yh[(size_t)MROWS * INNER];
__device__ __align__(16) __nv_bfloat16 g_yl[(size_t)MROWS * INNER];
__device__ __align__(16) __nv_bfloat16 g_xsh[(size_t)MROWS * INNER];
__device__ __align__(16) __nv_bfloat16 g_xsl[(size_t)MROWS * INNER];
__device__ __align__(16) __nv_bfloat16 g_wxh[(size_t)128 * INNER];
__device__ __align__(16) __nv_bfloat16 g_wxl[(size_t)128 * INNER];
__device__ __align__(16) __nv_bfloat16 g_dbh[(size_t)MROWS * DTR];
__device__ __align__(16) __nv_bfloat16 g_dbl[(size_t)MROWS * DTR];
__device__ __align__(16) __nv_bfloat16 g_wdh[(size_t)INNER * DTR];
__device__ __align__(16) __nv_bfloat16 g_wdl[(size_t)INNER * DTR];

// ============================================================
// Fused fp32 -> bf16 hi/lo split for all 5 tensors + W_x pad.
// Compile-time segment offsets (in float4 units).
// ============================================================
#define SP_N0 (MROWS * DMODEL / 4)          // x       1048576
#define SP_N1 (NIN * DMODEL / 4)            // W_in    1048576
#define SP_N2 (DMODEL * INNER / 4)          // W_out    524288
#define SP_N3 (XD * INNER / 4)              // W_x       49152
#define SP_N4 (INNER * DTR / 4)             // W_dt      32768
#define SP_O1 (SP_N0)
#define SP_O2 (SP_O1 + SP_N1)
#define SP_O3 (SP_O2 + SP_N2)
#define SP_O4 (SP_O3 + SP_N3)
#define SP_O5 (SP_O4 + SP_N4)               // 2703360
#define SP_PAD 8192                          // 32*2048 bf16 / 8 per plane
#define SP_TOT (SP_O5 + SP_PAD)

__device__ __forceinline__ void split_one(const float4* src, __nv_bfloat162* hi,
                                          __nv_bfloat162* lo, int i)
{
    float4 f = src[i];
    __nv_bfloat16 hx = __float2bfloat16(f.x), hy = __float2bfloat16(f.y);
    __nv_bfloat16 hz = __float2bfloat16(f.z), hw = __float2bfloat16(f.w);
    __nv_bfloat16 lx = __float2bfloat16(f.x - __bfloat162float(hx));
    __nv_bfloat16 ly = __float2bfloat16(f.y - __bfloat162float(hy));
    __nv_bfloat16 lz = __float2bfloat16(f.z - __bfloat162float(hz));
    __nv_bfloat16 lw = __float2bfloat16(f.w - __bfloat162float(hw));
    hi[i * 2 + 0] = __halves2bfloat162(hx, hy);
    hi[i * 2 + 1] = __halves2bfloat162(hz, hw);
    lo[i * 2 + 0] = __halves2bfloat162(lx, ly);
    lo[i * 2 + 1] = __halves2bfloat162(lz, lw);
}

__global__ void split_all_kernel(const float4* __restrict__ x,
                                 const float4* __restrict__ W_in,
                                 const float4* __restrict__ W_out,
                                 const float4* __restrict__ W_x,
                                 const float4* __restrict__ W_dt)
{
    int i = blockIdx.x * blockDim.x + threadIdx.x;
    if (i < SP_O1) {
        split_one(x, (__nv_bfloat162*)g_xh, (__nv_bfloat162*)g_xl, i);
    } else if (i < SP_O2) {
        split_one(W_in, (__nv_bfloat162*)g_wih, (__nv_bfloat162*)g_wil, i - SP_O1);
    } else if (i < SP_O3) {
        split_one(W_out, (__nv_bfloat162*)g_woh, (__nv_bfloat162*)g_wol, i - SP_O2);
    } else if (i < SP_O4) {
        split_one(W_x, (__nv_bfloat162*)g_wxh, (__nv_bfloat162*)g_wxl, i - SP_O3);
    } else if (i < SP_O5) {
        split_one(W_dt, (__nv_bfloat162*)g_wdh, (__nv_bfloat162*)g_wdl, i - SP_O4);
    } else if (i < SP_TOT) {
        int j = i - SP_O5;   // 16B chunks of the 96..127-row pad region
        ((uint4*)(g_wxh + (size_t)96 * INNER))[j] = make_uint4(0, 0, 0, 0);
        ((uint4*)(g_wxl + (size_t)96 * INNER))[j] = make_uint4(0, 0, 0, 0);
    }
}

// sum x_dbl split-K partials -> g_xdbl; also emit bf16 planes of cols 0..63
__global__ void reduce_xdbl_kernel()
{
    int i = blockIdx.x * blockDim.x + threadIdx.x;
    if (i >= MROWS * XD) return;
    float s = g_xdp[i] + g_xdp[(size_t)MROWS * XD + i]
            + g_xdp[2 * (size_t)MROWS * XD + i] + g_xdp[3 * (size_t)MROWS * XD + i];
    g_xdbl[i] = s;
    int col = i % XD;
    if (col < DTR) {
        int m = i / XD;
        __nv_bfloat16 vh = __float2bfloat16(s);
        __nv_bfloat16 vl = __float2bfloat16(s - __bfloat162float(vh));
        g_dbh[(size_t)m * DTR + col] = vh;
        g_dbl[(size_t)m * DTR + col] = vl;
    }
}

// ============================================================
// tcgen05 split-GEMM core helpers
// ============================================================
#define TC_BM 128
#define TC_BN 128
#define TC_BK 64
#define TC_TILE_BYTES 16384
#define TC_STAGE_BYTES (4 * TC_TILE_BYTES)
#define TC_SMEM_BYTES (1024 + 2 * TC_STAGE_BYTES)
#define TC_DT_SMEM (1024 + 4 * TC_TILE_BYTES)
#define TC_IDESC 0x8200490u

__device__ __forceinline__ uint32_t smem_u32(const void* p) {
    uint32_t a;
    asm("{ .reg .u64 t; cvta.to.shared.u64 t, %1; cvt.u32.u64 %0, t; }"
        : "=r"(a) : "l"(p));
    return a;
}

#if TC_OK
__device__ __forceinline__ uint64_t make_sw128_desc(uint32_t addr) {
    return ( (uint64_t)2 << 61 ) | ( (uint64_t)1 << 46 )
         | ( (uint64_t)64 << 32 ) | ( (uint64_t)1 << 16 )
         | ( (uint64_t)(addr >> 4) & 0x3FFF );
}

__device__ __forceinline__ void mma_ss_bf16(uint32_t d, uint64_t ad, uint64_t bd,
                                            uint32_t acc) {
    asm volatile(
        "{\n\t.reg .pred p;\n\t"
        "setp.ne.u32 p, %4, 0;\n\t"
        "tcgen05.mma.cta_group::1.kind::f16 [%0], %1, %2, %3, {%5, %5, %5, %5}, p;\n\t}"
        :: "r"(d), "l"(ad), "l"(bd), "r"(TC_IDESC), "r"(acc), "r"(0u)
        : "memory");
}

__device__ __forceinline__ void mbar_wait_parity(uint32_t mbar, uint32_t parity) {
    asm volatile(
        "{\n\t.reg .pred P;\n\t"
        "WL_%=:\n\t"
        "mbarrier.try_wait.parity.acquire.cta.shared::cta.b64 P, [%0], %1, 0x989680;\n\t"
        "@!P bra WL_%=;\n\t}"
        :: "r"(mbar), "r"(parity) : "memory");
}

__device__ __forceinline__ void tmem_ld32(uint32_t* r, uint32_t addr) {
    asm volatile(
        "tcgen05.ld.sync.aligned.32x32b.x32.b32 "
        "{%0, %1, %2, %3, %4, %5, %6, %7, "
        " %8, %9, %10, %11, %12, %13, %14, %15, "
        " %16, %17, %18, %19, %20, %21, %22, %23, "
        " %24, %25, %26, %27, %28, %29, %30, %31}, [%32];"
        : "=r"(r[0]), "=r"(r[1]), "=r"(r[2]), "=r"(r[3]),
          "=r"(r[4]), "=r"(r[5]), "=r"(r[6]), "=r"(r[7]),
          "=r"(r[8]), "=r"(r[9]), "=r"(r[10]), "=r"(r[11]),
          "=r"(r[12]), "=r"(r[13]), "=r"(r[14]), "=r"(r[15]),
          "=r"(r[16]), "=r"(r[17]), "=r"(r[18]), "=r"(r[19]),
          "=r"(r[20]), "=r"(r[21]), "=r"(r[22]), "=r"(r[23]),
          "=r"(r[24]), "=r"(r[25]), "=r"(r[26]), "=r"(r[27]),
          "=r"(r[28]), "=r"(r[29]), "=r"(r[30]), "=r"(r[31])
        : "r"(addr));
}

__device__ __forceinline__ void copy_tile(const __nv_bfloat16* __restrict__ plane,
                                          int row0, int k0, int ld,
                                          uint32_t dst, int tid)
{
#pragma unroll
    for (int p = 0; p < 4; p++) {
        int idx = p * 256 + tid;
        int r = idx >> 3;
        int b = (idx & 7) << 4;
        uint32_t off = (uint32_t)(r * 128 + b);
        uint32_t swz = off ^ ((off >> 3) & 0x70);
        const void* src = plane + (size_t)(row0 + r) * ld + k0 + (b >> 1);
        asm volatile("cp.async.cg.shared.global [%0], [%1], 16;"
                     :: "r"(dst + swz), "l"(src) : "memory");
    }
}
#endif // TC_OK

// ============================================================
// General pipelined split-GEMM. gridDim.z = split-K slices.
// ============================================================
__global__ __launch_bounds__(256) void tc_gemm_split(
    const __nv_bfloat16* __restrict__ Ah, const __nv_bfloat16* __restrict__ Al,
    const __nv_bfloat16* __restrict__ Bh, const __nv_bfloat16* __restrict__ Bl,
    float* __restrict__ C, int ldA, int ldB, int Kloop, int ldC, int ncols,
    int Kz, size_t Cz)
{
#if TC_OK
    extern __shared__ char smem[];
    const uint32_t sb = smem_u32(smem);
    const uint32_t MBAR0 = sb + 8;
    const uint32_t MBAR1 = sb + 16;
    const uint32_t DONE  = sb + 24;
    const uint32_t S_DATA = sb + 1024;

    const int tid = threadIdx.x;
    const int wid = tid >> 5, lid = tid & 31;
    const int bm = blockIdx.y * TC_BM;
    const int bn = blockIdx.x * TC_BN;
    const int koff = blockIdx.z * Kz;
    C += (size_t)blockIdx.z * Cz;

    if (wid == 0) {
        asm volatile(
            "tcgen05.alloc.cta_group::1.sync.aligned.shared::cta.b32 [%0], %1;"
            :: "r"(sb), "r"(128u) : "memory");
    }
    if (tid == 0) {
        asm volatile("mbarrier.init.shared.b64 [%0], 1;" :: "r"(MBAR0) : "memory");
        asm volatile("mbarrier.init.shared.b64 [%0], 1;" :: "r"(MBAR1) : "memory");
        asm volatile("mbarrier.init.shared.b64 [%0], 1;" :: "r"(DONE)  : "memory");
    }
    __syncthreads();
    uint32_t tmem;
    asm volatile("ld.shared.b32 %0, [%1];" : "=r"(tmem) : "r"(sb));

    const int nch = Kloop / TC_BK;

    {
        uint32_t st = S_DATA;
        copy_tile(Ah, bm, koff, ldA, st + 0 * TC_TILE_BYTES, tid);
        copy_tile(Al, bm, koff, ldA, st + 1 * TC_TILE_BYTES, tid);
        copy_tile(Bh, bn, koff, ldB, st + 2 * TC_TILE_BYTES, tid);
        copy_tile(Bl, bn, koff, ldB, st + 3 * TC_TILE_BYTES, tid);
        asm volatile("cp.async.commit_group;" ::: "memory");
    }

    for (int ch = 0; ch < nch; ch++) {
        const int s = ch & 1;
        if (ch + 1 < nch) {
            const int nx = ch + 1, t = nx & 1;
            if (nx >= 2) {
                uint32_t py = (uint32_t)(((nx - 2 - t) >> 1) & 1);
                mbar_wait_parity(t ? MBAR1 : MBAR0, py);
            }
            const int k0 = koff + nx * TC_BK;
            uint32_t st = S_DATA + (uint32_t)t * TC_STAGE_BYTES;
            copy_tile(Ah, bm, k0, ldA, st + 0 * TC_TILE_BYTES, tid);
            copy_tile(Al, bm, k0, ldA, st + 1 * TC_TILE_BYTES, tid);
            copy_tile(Bh, bn, k0, ldB, st + 2 * TC_TILE_BYTES, tid);
            copy_tile(Bl, bn, k0, ldB, st + 3 * TC_TILE_BYTES, tid);
            asm volatile("cp.async.commit_group;" ::: "memory");
            asm volatile("cp.async.wait_group 1;" ::: "memory");
        } else {
            asm volatile("cp.async.wait_group 0;" ::: "memory");
        }
        asm volatile("fence.proxy.async.shared::cta;" ::: "memory");
        __syncthreads();

        if (tid == 0) {
            uint32_t base = S_DATA + (uint32_t)s * TC_STAGE_BYTES;
            uint64_t adh = make_sw128_desc(base);
            uint64_t adl = make_sw128_desc(base + 1 * TC_TILE_BYTES);
            uint64_t bdh = make_sw128_desc(base + 2 * TC_TILE_BYTES);
            uint64_t bdl = make_sw128_desc(base + 3 * TC_TILE_BYTES);
#pragma unroll
            for (int ks = 0; ks < 4; ks++) {
                mma_ss_bf16(tmem, adh + ks * 2, bdh + ks * 2,
                            (uint32_t)(ch != 0 || ks != 0));
                mma_ss_bf16(tmem, adl + ks * 2, bdh + ks * 2, 1u);
                mma_ss_bf16(tmem, adh + ks * 2, bdl + ks * 2, 1u);
            }
            asm volatile(
                "tcgen05.commit.cta_group::1.mbarrier::arrive::one.shared::cluster.b64 [%0];"
                :: "r"(s ? MBAR1 : MBAR0) : "memory");
        }
    }

    if (tid == 0) {
        asm volatile(
            "tcgen05.commit.cta_group::1.mbarrier::arrive::one.shared::cluster.b64 [%0];"
            :: "r"(DONE) : "memory");
    }
    mbar_wait_parity(DONE, 0);
    asm volatile("tcgen05.fence::after_thread_sync;" ::: "memory");

    if (wid < 4) {
        int m = bm + wid * 32 + lid;
        float* cp = C + (size_t)m * ldC + bn;
#pragma unroll
        for (int base = 0; base < 128; base += 32) {
            if (bn + base >= ncols) break;
            uint32_t r[32];
            tmem_ld32(r, tmem + base);
            asm volatile("tcgen05.wait::ld.sync.aligned;" ::: "memory");
#pragma unroll
            for (int j = 0; j < 32; j += 4) {
                if (bn + base + j < ncols) {
                    float4 v = make_float4(__uint_as_float(r[j]), __uint_as_float(r[j + 1]),
                                           __uint_as_float(r[j + 2]), __uint_as_float(r[j + 3]));
                    *(float4*)(cp + base + j) = v;
                }
            }
        }
    }
    __syncthreads();
    if (tid == 0) {
        asm volatile("mbarrier.inval.shared.b64 [%0];" :: "r"(MBAR0) : "memory");
        asm volatile("mbarrier.inval.shared.b64 [%0];" :: "r"(MBAR1) : "memory");
        asm volatile("mbarrier.inval.shared.b64 [%0];" :: "r"(DONE)  : "memory");
    }
    __syncthreads();
    if (wid == 0) {
        asm volatile("tcgen05.relinquish_alloc_permit.cta_group::1.sync.aligned;");
        asm volatile("tcgen05.dealloc.cta_group::1.sync.aligned.b32 %0, %1;"
                     :: "r"(tmem), "r"(128u));
    }
#endif // TC_OK
}

// ============================================================
// dt GEMM on tcgen05: K=64 single chunk; epilogue = +b_dt then log(2+e^z)
// ============================================================
__global__ __launch_bounds__(256) void tc_dt_gemm(const float* __restrict__ b_dt)
{
#if TC_OK
    extern __shared__ char smem[];
    const uint32_t sb = smem_u32(smem);
    const uint32_t MBAR = sb + 8;
    const uint32_t S_AH = sb + 1024;
    const uint32_t S_AL = S_AH + TC_TILE_BYTES;
    const uint32_t S_BH = S_AL + TC_TILE_BYTES;
    const uint32_t S_BL = S_BH + TC_TILE_BYTES;

    const int tid = threadIdx.x;
    const int wid = tid >> 5, lid = tid & 31;
    const int bm = blockIdx.y * TC_BM;
    const int bn = blockIdx.x * TC_BN;

    if (wid == 0) {
        asm volatile(
            "tcgen05.alloc.cta_group::1.sync.aligned.shared::cta.b32 [%0], %1;"
            :: "r"(sb), "r"(128u) : "memory");
    }
    if (tid == 0)
        asm volatile("mbarrier.init.shared.b64 [%0], 1;" :: "r"(MBAR) : "memory");
    __syncthreads();
    uint32_t tmem;
    asm volatile("ld.shared.b32 %0, [%1];" : "=r"(tmem) : "r"(sb));

    copy_tile(g_dbh, bm, 0, DTR, S_AH, tid);
    copy_tile(g_dbl, bm, 0, DTR, S_AL, tid);
    copy_tile(g_wdh, bn, 0, DTR, S_BH, tid);
    copy_tile(g_wdl, bn, 0, DTR, S_BL, tid);
    asm volatile("cp.async.commit_group;" ::: "memory");
    asm volatile("cp.async.wait_group 0;" ::: "memory");
    asm volatile("fence.proxy.async.shared::cta;" ::: "memory");
    __syncthreads();

    if (tid == 0) {
        uint64_t adh = make_sw128_desc(S_AH), adl = make_sw128_desc(S_AL);
        uint64_t bdh = make_sw128_desc(S_BH), bdl = make_sw128_desc(S_BL);
#pragma unroll
        for (int ks = 0; ks < 4; ks++) {
            mma_ss_bf16(tmem, adh + ks * 2, bdh + ks * 2, (uint32_t)(ks != 0));
            mma_ss_bf16(tmem, adl + ks * 2, bdh + ks * 2, 1u);
            mma_ss_bf16(tmem, adh + ks * 2, bdl + ks * 2, 1u);
        }
        asm volatile(
            "tcgen05.commit.cta_group::1.mbarrier::arrive::one.shared::cluster.b64 [%0];"
            :: "r"(MBAR) : "memory");
    }
    mbar_wait_parity(MBAR, 0);
    asm volatile("tcgen05.fence::after_thread_sync;" ::: "memory");

    if (wid < 4) {
        int m = bm + wid * 32 + lid;
        float* cp = g_dt + (size_t)m * INNER + bn;
#pragma unroll
        for (int base = 0; base < 128; base += 32) {
            uint32_t r[32];
            tmem_ld32(r, tmem + base);
            asm volatile("tcgen05.wait::ld.sync.aligned;" ::: "memory");
#pragma unroll
            for (int j = 0; j < 32; j++) {
                float z = __uint_as_float(r[j]) + b_dt[bn + base + j];
                float mz = fmaxf(z, 0.f);
                cp[base + j] = mz + __logf(2.f * __expf(-mz) + __expf(z - mz));
            }
        }
    }
    __syncthreads();
    if (tid == 0)
        asm volatile("mbarrier.inval.shared.b64 [%0];" :: "r"(MBAR) : "memory");
    __syncthreads();
    if (wid == 0) {
        asm volatile("tcgen05.relinquish_alloc_permit.cta_group::1.sync.aligned;");
        asm volatile("tcgen05.dealloc.cta_group::1.sync.aligned.b32 %0, %1;"
                     :: "r"(tmem), "r"(128u));
    }
#endif // TC_OK
}

// ============================================================
// Depthwise causal conv + bias + silu
// ============================================================
__global__ void conv_silu_kernel(const float* __restrict__ conv_w,
                                 const float* __restrict__ conv_b)
{
    int idx = blockIdx.x * blockDim.x + threadIdx.x;
    if (idx >= MROWS * INNER) return;
    int c = idx & (INNER - 1);
    int m = idx >> 11;
    int l = m & (LSEQ - 1);
    float w0 = conv_w[c * 4 + 0], w1 = conv_w[c * 4 + 1];
    float w2 = conv_w[c * 4 + 2], w3 = conv_w[c * 4 + 3];
    float s = conv_b[c];
    s = fmaf(w3, g_xr[(size_t)m * NIN + c], s);
    if (l >= 1) s = fmaf(w2, g_xr[(size_t)(m - 1) * NIN + c], s);
    if (l >= 2) s = fmaf(w1, g_xr[(size_t)(m - 2) * NIN + c], s);
    if (l >= 3) s = fmaf(w0, g_xr[(size_t)(m - 3) * NIN + c], s);
    float sig = 1.f / (1.f + __expf(-s));
    float v = s * sig;
    g_xs[idx] = v;
    __nv_bfloat16 vh = __float2bfloat16(v);
    __nv_bfloat16 vl = __float2bfloat16(v - __bfloat162float(vh));
    g_xsh[idx] = vh;
    g_xsl[idx] = vl;
}

// ============================================================
// Chunked selective scan, NCHK=32/CLEN=64, software-pipelined x4.
// w = b*(NCHK*1024) + c*1024 + dpair
// ============================================================
__global__ __launch_bounds__(256) void scanA_kernel(const float* __restrict__ A_log)
{
    int w = blockIdx.x * 8 + (threadIdx.x >> 5);
    int lane = threadIdx.x & 31;
    int dpair = w & 1023;
    int c = (w >> 10) & (NCHK - 1);
    int b = w >> 15;
    int d = dpair * 2 + ((lane >> 4) & 1);
    int n = lane & 15;

    float a = -__expf(A_log[d * DST + n]);
    float h = 0.f, dts = 0.f;
    size_t m0 = (size_t)b * LSEQ + c * CLEN;
    for (int tt = 0; tt < CLEN; tt += 4) {
        size_t m = m0 + tt;
        // batch all loads first (MLP)
        float dt0 = g_dt[(m + 0) * INNER + d], dt1 = g_dt[(m + 1) * INNER + d];
        float dt2 = g_dt[(m + 2) * INNER + d], dt3 = g_dt[(m + 3) * INNER + d];
        float xv0 = g_xs[(m + 0) * INNER + d], xv1 = g_xs[(m + 1) * INNER + d];
        float xv2 = g_xs[(m + 2) * INNER + d], xv3 = g_xs[(m + 3) * INNER + d];
        float B0 = g_xdbl[(m + 0) * XD + DTR + n], B1 = g_xdbl[(m + 1) * XD + DTR + n];
        float B2 = g_xdbl[(m + 2) * XD + DTR + n], B3 = g_xdbl[(m + 3) * XD + DTR + n];
        h = fmaf(__expf(dt0 * a), h, dt0 * B0 * xv0);
        h = fmaf(__expf(dt1 * a), h, dt1 * B1 * xv1);
        h = fmaf(__expf(dt2 * a), h, dt2 * B2 * xv2);
        h = fmaf(__expf(dt3 * a), h, dt3 * B3 * xv3);
        dts += dt0 + dt1 + dt2 + dt3;
    }
    size_t slot = (size_t)(b * NCHK + c) * INNER + d;
    g_hc[slot * DST + n] = h;
    if (n == 0) g_dts[slot] = dts;
}

__global__ __launch_bounds__(256) void scanB_kernel(const float* __restrict__ A_log)
{
    int idx = blockIdx.x * 256 + threadIdx.x;       // 0..65535
    int n = idx & 15;
    int d = (idx >> 4) & (INNER - 1);
    int b = idx >> 15;
    float a = -__expf(A_log[d * DST + n]);
    float s = 0.f;
#pragma unroll
    for (int c = 0; c < NCHK; c++) {
        size_t slot = (size_t)(b * NCHK + c) * INNER + d;
        g_hi[slot * DST + n] = s;
        s = fmaf(__expf(a * g_dts[slot]), s, g_hc[slot * DST + n]);
    }
}

__global__ __launch_bounds__(256) void scanC_kernel(const float* __restrict__ A_log,
                                                    const float* __restrict__ D_par)
{
    int w = blockIdx.x * 8 + (threadIdx.x >> 5);
    int lane = threadIdx.x & 31;
    int dpair = w & 1023;
    int c = (w >> 10) & (NCHK - 1);
    int b = w >> 15;
    int d = dpair * 2 + ((lane >> 4) & 1);
    int n = lane & 15;

    float a = -__expf(A_log[d * DST + n]);
    float Dv = D_par[d];
    size_t slot = (size_t)(b * NCHK + c) * INNER + d;
    float h = g_hi[slot * DST + n];

    size_t m0 = (size_t)b * LSEQ + c * CLEN;
    for (int tt = 0; tt < CLEN; tt += 4) {
        size_t m = m0 + tt;
        float dt0 = g_dt[(m + 0) * INNER + d], dt1 = g_dt[(m + 1) * INNER + d];
        float dt2 = g_dt[(m + 2) * INNER + d], dt3 = g_dt[(m + 3) * INNER + d];
        float xv0 = g_xs[(m + 0) * INNER + d], xv1 = g_xs[(m + 1) * INNER + d];
        float xv2 = g_xs[(m + 2) * INNER + d], xv3 = g_xs[(m + 3) * INNER + d];
        float B0 = g_xdbl[(m + 0) * XD + DTR + n], B1 = g_xdbl[(m + 1) * XD + DTR + n];
        float B2 = g_xdbl[(m + 2) * XD + DTR + n], B3 = g_xdbl[(m + 3) * XD + DTR + n];
        float C0 = g_xdbl[(m + 0) * XD + DTR + DST + n], C1 = g_xdbl[(m + 1) * XD + DTR + DST + n];
        float C2 = g_xdbl[(m + 2) * XD + DTR + DST + n], C3 = g_xdbl[(m + 3) * XD + DTR + DST + n];
        float r0 = 0.f, r1 = 0.f, r2 = 0.f, r3 = 0.f;
        if (n == 0) {
            r0 = g_xr[(m + 0) * NIN + INNER + d]; r1 = g_xr[(m + 1) * NIN + INNER + d];
            r2 = g_xr[(m + 2) * NIN + INNER + d]; r3 = g_xr[(m + 3) * NIN + INNER + d];
        }
#pragma unroll
        for (int q = 0; q < 4; q++) {
            float dt = q == 0 ? dt0 : q == 1 ? dt1 : q == 2 ? dt2 : dt3;
            float xv = q == 0 ? xv0 : q == 1 ? xv1 : q == 2 ? xv2 : xv3;
            float Bn = q == 0 ? B0 : q == 1 ? B1 : q == 2 ? B2 : B3;
            float Cn = q == 0 ? C0 : q == 1 ? C1 : q == 2 ? C2 : C3;
            float rv = q == 0 ? r0 : q == 1 ? r1 : q == 2 ? r2 : r3;
            h = fmaf(__expf(dt * a), h, dt * Bn * xv);
            float pv = h * Cn;
            pv += __shfl_xor_sync(0xffffffffu, pv, 8);
            pv += __shfl_xor_sync(0xffffffffu, pv, 4);
            pv += __shfl_xor_sync(0xffffffffu, pv, 2);
            pv += __shfl_xor_sync(0xffffffffu, pv, 1);
            if (n == 0) {
                float silu_r = rv / (1.f + __expf(-rv));
                float v = (pv + xv * Dv) * silu_r;
                __nv_bfloat16 vh = __float2bfloat16(v);
                __nv_bfloat16 vl = __float2bfloat16(v - __bfloat162float(vh));
                g_yh[(m + q) * INNER + d] = vh;
                g_yl[(m + q) * INNER + d] = vl;
            }
        }
    }
}

// ============================================================
extern "C" void kernel_launch(void* const* d_in, const int* in_sizes, int n_in,
                              void* d_out, int out_size)
{
    const float* x      = (const float*)d_in[0];
    const float* W_in   = (const float*)d_in[1];
    const float* conv_w = (const float*)d_in[2];
    const float* conv_b = (const float*)d_in[3];
    const float* W_x    = (const float*)d_in[4];
    const float* W_dt   = (const float*)d_in[5];
    const float* b_dt   = (const float*)d_in[6];
    const float* A_log  = (const float*)d_in[7];
    const float* D_par  = (const float*)d_in[8];
    const float* W_out  = (const float*)d_in[9];
    float* out = (float*)d_out;

    float *xr_p, *xdp_p;
    __nv_bfloat16 *xh_p, *xl_p, *wih_p, *wil_p, *woh_p, *wol_p, *yh_p, *yl_p;
    __nv_bfloat16 *xsh_p, *xsl_p, *wxh_p, *wxl_p;
    cudaGetSymbolAddress((void**)&xr_p,   g_xr);
    cudaGetSymbolAddress((void**)&xdp_p,  g_xdp);
    cudaGetSymbolAddress((void**)&xh_p,   g_xh);
    cudaGetSymbolAddress((void**)&xl_p,   g_xl);
    cudaGetSymbolAddress((void**)&wih_p,  g_wih);
    cudaGetSymbolAddress((void**)&wil_p,  g_wil);
    cudaGetSymbolAddress((void**)&woh_p,  g_woh);
    cudaGetSymbolAddress((void**)&wol_p,  g_wol);
    cudaGetSymbolAddress((void**)&yh_p,   g_yh);
    cudaGetSymbolAddress((void**)&yl_p,   g_yl);
    cudaGetSymbolAddress((void**)&xsh_p,  g_xsh);
    cudaGetSymbolAddress((void**)&xsl_p,  g_xsl);
    cudaGetSymbolAddress((void**)&wxh_p,  g_wxh);
    cudaGetSymbolAddress((void**)&wxl_p,  g_wxl);

    cudaFuncSetAttribute(tc_gemm_split,
                         cudaFuncAttributeMaxDynamicSharedMemorySize, TC_SMEM_BYTES);
    cudaFuncSetAttribute(tc_dt_gemm,
                         cudaFuncAttributeMaxDynamicSharedMemorySize, TC_DT_SMEM);

    // 0) one fused bf16 split pass (x, W_in, W_out, W_x, W_dt, + W_x pad)
    split_all_kernel<<<(SP_TOT + 255) / 256, 256>>>(
        (const float4*)x, (const float4*)W_in, (const float4*)W_out,
        (const float4*)W_x, (const float4*)W_dt);

    // 1) xr = x @ W_in^T
    tc_gemm_split<<<dim3(NIN / TC_BN, MROWS / TC_BM, 1), 256, TC_SMEM_BYTES>>>(
        xh_p, xl_p, wih_p, wil_p, xr_p, DMODEL, DMODEL, DMODEL, NIN, NIN, 0, 0);

    // 2) depthwise causal conv + silu
    conv_silu_kernel<<<(MROWS * INNER + 255) / 256, 256>>>(conv_w, conv_b);

    // 3) x_dbl split-K x4, then reduce (+ dt-input planes)
    tc_gemm_split<<<dim3(1, MROWS / TC_BM, KSLC), 256, TC_SMEM_BYTES>>>(
        xsh_p, xsl_p, wxh_p, wxl_p, xdp_p, INNER, INNER, INNER / KSLC, XD, XD,
        INNER / KSLC, (size_t)MROWS * XD);
    reduce_xdbl_kernel<<<(MROWS * XD + 255) / 256, 256>>>();

    // 4) dt = log(2 + exp(xdbl[:,:64] @ W_dt^T + b_dt))
    tc_dt_gemm<<<dim3(INNER / TC_BN, MROWS / TC_BM), 256, TC_DT_SMEM>>>(b_dt);

    // 5) chunked selective scan (NCHK=32 -> 65536 warps for A/C)
    scanA_kernel<<<8192, 256>>>(A_log);
    scanB_kernel<<<256, 256>>>(A_log);
    scanC_kernel<<<8192, 256>>>(A_log, D_par);

    // 6) out = y @ W_out^T
    tc_gemm_split<<<dim3(DMODEL / TC_BN, MROWS / TC_BM, 1), 256, TC_SMEM_BYTES>>>(
        yh_p, yl_p, woh_p, wol_p, out, INNER, INNER, INNER, DMODEL, DMODEL, 0, 0);
}

// round 16
// speedup vs baseline: 9.1401x; 1.0128x over previous
#include <cuda_runtime.h>
#include <cuda_bf16.h>
#include <math.h>
#include <stdint.h>

#define BSZ    2
#define LSEQ   2048
#define DMODEL 1024
#define INNER  2048
#define MROWS  4096      // BSZ*LSEQ
#define NIN    4096      // 2*INNER
#define DTR    64
#define DST    16
#define XD     96        // DTR + 2*DST
#define NCHK   64        // scan chunks
#define CLEN   32        // LSEQ / NCHK
#define KSLC   4         // x_dbl split-K slices

#if defined(__CUDA_ARCH_FEAT_SM103_ALL) || defined(__CUDA_ARCH_FEAT_SM100_ALL)
#define TC_OK 1
#else
#define TC_OK 0
#endif

// ---- scratch (device globals; no allocation allowed) ----
__device__ float g_xr[(size_t)MROWS * NIN];
__device__ float g_xs[(size_t)MROWS * INNER];
__device__ float g_xdbl[(size_t)MROWS * XD];
__device__ float g_xdp[(size_t)KSLC * MROWS * XD];
__device__ float g_dt[(size_t)MROWS * INNER];
__device__ float g_hc[(size_t)BSZ * NCHK * INNER * DST];
__device__ float g_hi[(size_t)BSZ * NCHK * INNER * DST];
__device__ float g_dts[(size_t)BSZ * NCHK * INNER];
__device__ __align__(16) __nv_bfloat16 g_xh[(size_t)MROWS * DMODEL];
__device__ __align__(16) __nv_bfloat16 g_xl[(size_t)MROWS * DMODEL];
__device__ __align__(16) __nv_bfloat16 g_wih[(size_t)NIN * DMODEL];
__device__ __align__(16) __nv_bfloat16 g_wil[(size_t)NIN * DMODEL];
__device__ __align__(16) __nv_bfloat16 g_woh[(size_t)DMODEL * INNER];
__device__ __align__(16) __nv_bfloat16 g_wol[(size_t)DMODEL * INNER];
__device__ __align__(16) __nv_bfloat16 g_yh[(size_t)MROWS * INNER];
__device__ __align__(16) __nv_bfloat16 g_yl[(size_t)MROWS * INNER];
__device__ __align__(16) __nv_bfloat16 g_xsh[(size_t)MROWS * INNER];
__device__ __align__(16) __nv_bfloat16 g_xsl[(size_t)MROWS * INNER];
__device__ __align__(16) __nv_bfloat16 g_wxh[(size_t)128 * INNER];
__device__ __align__(16) __nv_bfloat16 g_wxl[(size_t)128 * INNER];
__device__ __align__(16) __nv_bfloat16 g_dbh[(size_t)MROWS * DTR];
__device__ __align__(16) __nv_bfloat16 g_dbl[(size_t)MROWS * DTR];
__device__ __align__(16) __nv_bfloat16 g_wdh[(size_t)INNER * DTR];
__device__ __align__(16) __nv_bfloat16 g_wdl[(size_t)INNER * DTR];

// ============================================================
// Fused fp32 -> bf16 hi/lo split for all 5 tensors + W_x pad
// ============================================================
#define SP_N0 (MROWS * DMODEL / 4)
#define SP_N1 (NIN * DMODEL / 4)
#define SP_N2 (DMODEL * INNER / 4)
#define SP_N3 (XD * INNER / 4)
#define SP_N4 (INNER * DTR / 4)
#define SP_O1 (SP_N0)
#define SP_O2 (SP_O1 + SP_N1)
#define SP_O3 (SP_O2 + SP_N2)
#define SP_O4 (SP_O3 + SP_N3)
#define SP_O5 (SP_O4 + SP_N4)
#define SP_PAD 8192
#define SP_TOT (SP_O5 + SP_PAD)

__device__ __forceinline__ void split_one(const float4* src, __nv_bfloat162* hi,
                                          __nv_bfloat162* lo, int i)
{
    float4 f = src[i];
    __nv_bfloat16 hx = __float2bfloat16(f.x), hy = __float2bfloat16(f.y);
    __nv_bfloat16 hz = __float2bfloat16(f.z), hw = __float2bfloat16(f.w);
    __nv_bfloat16 lx = __float2bfloat16(f.x - __bfloat162float(hx));
    __nv_bfloat16 ly = __float2bfloat16(f.y - __bfloat162float(hy));
    __nv_bfloat16 lz = __float2bfloat16(f.z - __bfloat162float(hz));
    __nv_bfloat16 lw = __float2bfloat16(f.w - __bfloat162float(hw));
    hi[i * 2 + 0] = __halves2bfloat162(hx, hy);
    hi[i * 2 + 1] = __halves2bfloat162(hz, hw);
    lo[i * 2 + 0] = __halves2bfloat162(lx, ly);
    lo[i * 2 + 1] = __halves2bfloat162(lz, lw);
}

__global__ void split_all_kernel(const float4* __restrict__ x,
                                 const float4* __restrict__ W_in,
                                 const float4* __restrict__ W_out,
                                 const float4* __restrict__ W_x,
                                 const float4* __restrict__ W_dt)
{
    int i = blockIdx.x * blockDim.x + threadIdx.x;
    if (i < SP_O1) {
        split_one(x, (__nv_bfloat162*)g_xh, (__nv_bfloat162*)g_xl, i);
    } else if (i < SP_O2) {
        split_one(W_in, (__nv_bfloat162*)g_wih, (__nv_bfloat162*)g_wil, i - SP_O1);
    } else if (i < SP_O3) {
        split_one(W_out, (__nv_bfloat162*)g_woh, (__nv_bfloat162*)g_wol, i - SP_O2);
    } else if (i < SP_O4) {
        split_one(W_x, (__nv_bfloat162*)g_wxh, (__nv_bfloat162*)g_wxl, i - SP_O3);
    } else if (i < SP_O5) {
        split_one(W_dt, (__nv_bfloat162*)g_wdh, (__nv_bfloat162*)g_wdl, i - SP_O4);
    } else if (i < SP_TOT) {
        int j = i - SP_O5;
        ((uint4*)(g_wxh + (size_t)96 * INNER))[j] = make_uint4(0, 0, 0, 0);
        ((uint4*)(g_wxl + (size_t)96 * INNER))[j] = make_uint4(0, 0, 0, 0);
    }
}

// sum x_dbl split-K partials -> g_xdbl; also emit bf16 planes of cols 0..63
__global__ void reduce_xdbl_kernel()
{
    int i = blockIdx.x * blockDim.x + threadIdx.x;
    if (i >= MROWS * XD) return;
    float s = g_xdp[i] + g_xdp[(size_t)MROWS * XD + i]
            + g_xdp[2 * (size_t)MROWS * XD + i] + g_xdp[3 * (size_t)MROWS * XD + i];
    g_xdbl[i] = s;
    int col = i % XD;
    if (col < DTR) {
        int m = i / XD;
        __nv_bfloat16 vh = __float2bfloat16(s);
        __nv_bfloat16 vl = __float2bfloat16(s - __bfloat162float(vh));
        g_dbh[(size_t)m * DTR + col] = vh;
        g_dbl[(size_t)m * DTR + col] = vl;
    }
}

// ============================================================
// tcgen05 split-GEMM helpers
// ============================================================
#define TC_BM 128
#define TC_BK 64
#define TC_A_BYTES 16384
#define TC_DT_SMEM (1024 + 4 * TC_A_BYTES)

__device__ __forceinline__ uint32_t smem_u32(const void* p) {
    uint32_t a;
    asm("{ .reg .u64 t; cvta.to.shared.u64 t, %1; cvt.u32.u64 %0, t; }"
        : "=r"(a) : "l"(p));
    return a;
}

#if TC_OK
__device__ __forceinline__ uint64_t make_sw128_desc(uint32_t addr) {
    return ( (uint64_t)2 << 61 ) | ( (uint64_t)1 << 46 )
         | ( (uint64_t)64 << 32 ) | ( (uint64_t)1 << 16 )
         | ( (uint64_t)(addr >> 4) & 0x3FFF );
}

__device__ __forceinline__ void mma_ss_bf16(uint32_t d, uint64_t ad, uint64_t bd,
                                            uint32_t idesc, uint32_t acc) {
    asm volatile(
        "{\n\t.reg .pred p;\n\t"
        "setp.ne.u32 p, %5, 0;\n\t"
        "tcgen05.mma.cta_group::1.kind::f16 [%0], %1, %2, %3, {%4, %4, %4, %4}, p;\n\t}"
        :: "r"(d), "l"(ad), "l"(bd), "r"(idesc), "r"(0u), "r"(acc)
        : "memory");
}

__device__ __forceinline__ void mbar_wait_parity(uint32_t mbar, uint32_t parity) {
    asm volatile(
        "{\n\t.reg .pred P;\n\t"
        "WL_%=:\n\t"
        "mbarrier.try_wait.parity.acquire.cta.shared::cta.b64 P, [%0], %1, 0x989680;\n\t"
        "@!P bra WL_%=;\n\t}"
        :: "r"(mbar), "r"(parity) : "memory");
}

__device__ __forceinline__ void tmem_ld32(uint32_t* r, uint32_t addr) {
    asm volatile(
        "tcgen05.ld.sync.aligned.32x32b.x32.b32 "
        "{%0, %1, %2, %3, %4, %5, %6, %7, "
        " %8, %9, %10, %11, %12, %13, %14, %15, "
        " %16, %17, %18, %19, %20, %21, %22, %23, "
        " %24, %25, %26, %27, %28, %29, %30, %31}, [%32];"
        : "=r"(r[0]), "=r"(r[1]), "=r"(r[2]), "=r"(r[3]),
          "=r"(r[4]), "=r"(r[5]), "=r"(r[6]), "=r"(r[7]),
          "=r"(r[8]), "=r"(r[9]), "=r"(r[10]), "=r"(r[11]),
          "=r"(r[12]), "=r"(r[13]), "=r"(r[14]), "=r"(r[15]),
          "=r"(r[16]), "=r"(r[17]), "=r"(r[18]), "=r"(r[19]),
          "=r"(r[20]), "=r"(r[21]), "=r"(r[22]), "=r"(r[23]),
          "=r"(r[24]), "=r"(r[25]), "=r"(r[26]), "=r"(r[27]),
          "=r"(r[28]), "=r"(r[29]), "=r"(r[30]), "=r"(r[31])
        : "r"(addr));
}

template<int ROWS>
__device__ __forceinline__ void copy_tile(const __nv_bfloat16* __restrict__ plane,
                                          int row0, int k0, int ld,
                                          uint32_t dst, int tid)
{
#pragma unroll
    for (int p = 0; p < ROWS / 32; p++) {
        int idx = p * 256 + tid;
        int r = idx >> 3;
        int b = (idx & 7) << 4;
        uint32_t off = (uint32_t)(r * 128 + b);
        uint32_t swz = off ^ ((off >> 3) & 0x70);
        const void* src = plane + (size_t)(row0 + r) * ld + k0 + (b >> 1);
        asm volatile("cp.async.cg.shared.global [%0], [%1], 16;"
                     :: "r"(dst + swz), "l"(src) : "memory");
    }
}
#endif // TC_OK

// ============================================================
// General pipelined split-GEMM, templated on BN (128 or 256).
// ============================================================
template<int BN_>
__global__ __launch_bounds__(256) void tc_gemm_split(
    const __nv_bfloat16* __restrict__ Ah, const __nv_bfloat16* __restrict__ Al,
    const __nv_bfloat16* __restrict__ Bh, const __nv_bfloat16* __restrict__ Bl,
    float* __restrict__ C, int ldA, int ldB, int Kloop, int ldC, int ncols,
    int Kz, size_t Cz)
{
#if TC_OK
    constexpr int B_BYTES = BN_ * 128;
    constexpr uint32_t STAGE = 2 * TC_A_BYTES + 2 * B_BYTES;
    constexpr uint32_t IDESC = 0x8000490u | ((BN_ / 8) << 17);

    extern __shared__ char smem[];
    const uint32_t sb = smem_u32(smem);
    const uint32_t MBAR0 = sb + 8;
    const uint32_t MBAR1 = sb + 16;
    const uint32_t DONE  = sb + 24;
    const uint32_t S_DATA = sb + 1024;

    const int tid = threadIdx.x;
    const int wid = tid >> 5, lid = tid & 31;
    const int bm = blockIdx.y * TC_BM;
    const int bn = blockIdx.x * BN_;
    const int koff = blockIdx.z * Kz;
    C += (size_t)blockIdx.z * Cz;

    if (wid == 0) {
        asm volatile(
            "tcgen05.alloc.cta_group::1.sync.aligned.shared::cta.b32 [%0], %1;"
            :: "r"(sb), "r"((uint32_t)BN_) : "memory");
    }
    if (tid == 0) {
        asm volatile("mbarrier.init.shared.b64 [%0], 1;" :: "r"(MBAR0) : "memory");
        asm volatile("mbarrier.init.shared.b64 [%0], 1;" :: "r"(MBAR1) : "memory");
        asm volatile("mbarrier.init.shared.b64 [%0], 1;" :: "r"(DONE)  : "memory");
    }
    __syncthreads();
    uint32_t tmem;
    asm volatile("ld.shared.b32 %0, [%1];" : "=r"(tmem) : "r"(sb));

    const int nch = Kloop / TC_BK;

    {
        uint32_t st = S_DATA;
        copy_tile<128>(Ah, bm, koff, ldA, st, tid);
        copy_tile<128>(Al, bm, koff, ldA, st + TC_A_BYTES, tid);
        copy_tile<BN_>(Bh, bn, koff, ldB, st + 2 * TC_A_BYTES, tid);
        copy_tile<BN_>(Bl, bn, koff, ldB, st + 2 * TC_A_BYTES + B_BYTES, tid);
        asm volatile("cp.async.commit_group;" ::: "memory");
    }

    for (int ch = 0; ch < nch; ch++) {
        const int s = ch & 1;
        if (ch + 1 < nch) {
            const int nx = ch + 1, t = nx & 1;
            if (nx >= 2) {
                uint32_t py = (uint32_t)(((nx - 2 - t) >> 1) & 1);
                mbar_wait_parity(t ? MBAR1 : MBAR0, py);
            }
            const int k0 = koff + nx * TC_BK;
            uint32_t st = S_DATA + (uint32_t)t * STAGE;
            copy_tile<128>(Ah, bm, k0, ldA, st, tid);
            copy_tile<128>(Al, bm, k0, ldA, st + TC_A_BYTES, tid);
            copy_tile<BN_>(Bh, bn, k0, ldB, st + 2 * TC_A_BYTES, tid);
            copy_tile<BN_>(Bl, bn, k0, ldB, st + 2 * TC_A_BYTES + B_BYTES, tid);
            asm volatile("cp.async.commit_group;" ::: "memory");
            asm volatile("cp.async.wait_group 1;" ::: "memory");
        } else {
            asm volatile("cp.async.wait_group 0;" ::: "memory");
        }
        asm volatile("fence.proxy.async.shared::cta;" ::: "memory");
        __syncthreads();

        if (tid == 0) {
            uint32_t base = S_DATA + (uint32_t)s * STAGE;
            uint64_t adh = make_sw128_desc(base);
            uint64_t adl = make_sw128_desc(base + TC_A_BYTES);
            uint64_t bdh = make_sw128_desc(base + 2 * TC_A_BYTES);
            uint64_t bdl = make_sw128_desc(base + 2 * TC_A_BYTES + B_BYTES);
#pragma unroll
            for (int ks = 0; ks < 4; ks++) {
                mma_ss_bf16(tmem, adh + ks * 2, bdh + ks * 2, IDESC,
                            (uint32_t)(ch != 0 || ks != 0));
                mma_ss_bf16(tmem, adl + ks * 2, bdh + ks * 2, IDESC, 1u);
                mma_ss_bf16(tmem, adh + ks * 2, bdl + ks * 2, IDESC, 1u);
            }
            asm volatile(
                "tcgen05.commit.cta_group::1.mbarrier::arrive::one.shared::cluster.b64 [%0];"
                :: "r"(s ? MBAR1 : MBAR0) : "memory");
        }
    }

    if (tid == 0) {
        asm volatile(
            "tcgen05.commit.cta_group::1.mbarrier::arrive::one.shared::cluster.b64 [%0];"
            :: "r"(DONE) : "memory");
    }
    mbar_wait_parity(DONE, 0);
    asm volatile("tcgen05.fence::after_thread_sync;" ::: "memory");

    if (wid < 4) {
        int m = bm + wid * 32 + lid;
        float* cp = C + (size_t)m * ldC + bn;
#pragma unroll
        for (int base = 0; base < BN_; base += 32) {
            if (bn + base >= ncols) break;
            uint32_t r[32];
            tmem_ld32(r, tmem + base);
            asm volatile("tcgen05.wait::ld.sync.aligned;" ::: "memory");
#pragma unroll
            for (int j = 0; j < 32; j += 4) {
                if (bn + base + j < ncols) {
                    float4 v = make_float4(__uint_as_float(r[j]), __uint_as_float(r[j + 1]),
                                           __uint_as_float(r[j + 2]), __uint_as_float(r[j + 3]));
                    *(float4*)(cp + base + j) = v;
                }
            }
        }
    }
    __syncthreads();
    if (tid == 0) {
        asm volatile("mbarrier.inval.shared.b64 [%0];" :: "r"(MBAR0) : "memory");
        asm volatile("mbarrier.inval.shared.b64 [%0];" :: "r"(MBAR1) : "memory");
        asm volatile("mbarrier.inval.shared.b64 [%0];" :: "r"(DONE)  : "memory");
    }
    __syncthreads();
    if (wid == 0) {
        asm volatile("tcgen05.relinquish_alloc_permit.cta_group::1.sync.aligned;");
        asm volatile("tcgen05.dealloc.cta_group::1.sync.aligned.b32 %0, %1;"
                     :: "r"(tmem), "r"((uint32_t)BN_));
    }
#endif // TC_OK
}

// ============================================================
// dt GEMM: K=64 single chunk; epilogue = +b_dt then log(2+e^z)
// ============================================================
__global__ __launch_bounds__(256) void tc_dt_gemm(const float* __restrict__ b_dt)
{
#if TC_OK
    extern __shared__ char smem[];
    const uint32_t sb = smem_u32(smem);
    const uint32_t MBAR = sb + 8;
    const uint32_t S_AH = sb + 1024;
    const uint32_t S_AL = S_AH + TC_A_BYTES;
    const uint32_t S_BH = S_AL + TC_A_BYTES;
    const uint32_t S_BL = S_BH + TC_A_BYTES;
    constexpr uint32_t IDESC = 0x8000490u | ((128 / 8) << 17);

    const int tid = threadIdx.x;
    const int wid = tid >> 5, lid = tid & 31;
    const int bm = blockIdx.y * TC_BM;
    const int bn = blockIdx.x * 128;

    if (wid == 0) {
        asm volatile(
            "tcgen05.alloc.cta_group::1.sync.aligned.shared::cta.b32 [%0], %1;"
            :: "r"(sb), "r"(128u) : "memory");
    }
    if (tid == 0)
        asm volatile("mbarrier.init.shared.b64 [%0], 1;" :: "r"(MBAR) : "memory");
    __syncthreads();
    uint32_t tmem;
    asm volatile("ld.shared.b32 %0, [%1];" : "=r"(tmem) : "r"(sb));

    copy_tile<128>(g_dbh, bm, 0, DTR, S_AH, tid);
    copy_tile<128>(g_dbl, bm, 0, DTR, S_AL, tid);
    copy_tile<128>(g_wdh, bn, 0, DTR, S_BH, tid);
    copy_tile<128>(g_wdl, bn, 0, DTR, S_BL, tid);
    asm volatile("cp.async.commit_group;" ::: "memory");
    asm volatile("cp.async.wait_group 0;" ::: "memory");
    asm volatile("fence.proxy.async.shared::cta;" ::: "memory");
    __syncthreads();

    if (tid == 0) {
        uint64_t adh = make_sw128_desc(S_AH), adl = make_sw128_desc(S_AL);
        uint64_t bdh = make_sw128_desc(S_BH), bdl = make_sw128_desc(S_BL);
#pragma unroll
        for (int ks = 0; ks < 4; ks++) {
            mma_ss_bf16(tmem, adh + ks * 2, bdh + ks * 2, IDESC, (uint32_t)(ks != 0));
            mma_ss_bf16(tmem, adl + ks * 2, bdh + ks * 2, IDESC, 1u);
            mma_ss_bf16(tmem, adh + ks * 2, bdl + ks * 2, IDESC, 1u);
        }
        asm volatile(
            "tcgen05.commit.cta_group::1.mbarrier::arrive::one.shared::cluster.b64 [%0];"
            :: "r"(MBAR) : "memory");
    }
    mbar_wait_parity(MBAR, 0);
    asm volatile("tcgen05.fence::after_thread_sync;" ::: "memory");

    if (wid < 4) {
        int m = bm + wid * 32 + lid;
        float* cp = g_dt + (size_t)m * INNER + bn;
#pragma unroll
        for (int base = 0; base < 128; base += 32) {
            uint32_t r[32];
            tmem_ld32(r, tmem + base);
            asm volatile("tcgen05.wait::ld.sync.aligned;" ::: "memory");
#pragma unroll
            for (int j = 0; j < 32; j++) {
                float z = __uint_as_float(r[j]) + b_dt[bn + base + j];
                float mz = fmaxf(z, 0.f);
                cp[base + j] = mz + __logf(2.f * __expf(-mz) + __expf(z - mz));
            }
        }
    }
    __syncthreads();
    if (tid == 0)
        asm volatile("mbarrier.inval.shared.b64 [%0];" :: "r"(MBAR) : "memory");
    __syncthreads();
    if (wid == 0) {
        asm volatile("tcgen05.relinquish_alloc_permit.cta_group::1.sync.aligned;");
        asm volatile("tcgen05.dealloc.cta_group::1.sync.aligned.b32 %0, %1;"
                     :: "r"(tmem), "r"(128u));
    }
#endif // TC_OK
}

// ============================================================
// Depthwise causal conv + bias + silu (float4: 4 channels/thread)
// ============================================================
__global__ void conv_silu_kernel(const float* __restrict__ conv_w,
                                 const float* __restrict__ conv_b)
{
    int i4 = blockIdx.x * blockDim.x + threadIdx.x;
    if (i4 >= MROWS * INNER / 4) return;
    int c4 = i4 & (INNER / 4 - 1);
    int m  = i4 >> 9;
    int l  = m & (LSEQ - 1);
    int c  = c4 * 4;

    // weights for 4 channels: conv_w[c..c+3][0..3] = 16 consecutive floats
    float4 wr0 = *(const float4*)(conv_w + c * 4 + 0);
    float4 wr1 = *(const float4*)(conv_w + c * 4 + 4);
    float4 wr2 = *(const float4*)(conv_w + c * 4 + 8);
    float4 wr3 = *(const float4*)(conv_w + c * 4 + 12);
    float4 bb  = *(const float4*)(conv_b + c);

    const float* base = g_xr + (size_t)m * NIN + c;
    float4 in0 = *(const float4*)base;
    float4 in1 = (l >= 1) ? *(const float4*)(base - NIN)     : make_float4(0, 0, 0, 0);
    float4 in2 = (l >= 2) ? *(const float4*)(base - 2 * NIN) : make_float4(0, 0, 0, 0);
    float4 in3 = (l >= 3) ? *(const float4*)(base - 3 * NIN) : make_float4(0, 0, 0, 0);

    float4 s;
    s.x = bb.x + wr0.w * in0.x + wr0.z * in1.x + wr0.y * in2.x + wr0.x * in3.x;
    s.y = bb.y + wr1.w * in0.y + wr1.z * in1.y + wr1.y * in2.y + wr1.x * in3.y;
    s.z = bb.z + wr2.w * in0.z + wr2.z * in1.z + wr2.y * in2.z + wr2.x * in3.z;
    s.w = bb.w + wr3.w * in0.w + wr3.z * in1.w + wr3.y * in2.w + wr3.x * in3.w;

    float4 v;
    v.x = s.x / (1.f + __expf(-s.x));
    v.y = s.y / (1.f + __expf(-s.y));
    v.z = s.z / (1.f + __expf(-s.z));
    v.w = s.w / (1.f + __expf(-s.w));

    *(float4*)(g_xs + (size_t)m * INNER + c) = v;

    __nv_bfloat16 h0 = __float2bfloat16(v.x), h1 = __float2bfloat16(v.y);
    __nv_bfloat16 h2 = __float2bfloat16(v.z), h3 = __float2bfloat16(v.w);
    __nv_bfloat162 hh0 = __halves2bfloat162(h0, h1);
    __nv_bfloat162 hh1 = __halves2bfloat162(h2, h3);
    *(uint2*)(g_xsh + (size_t)m * INNER + c) =
        make_uint2(*(uint32_t*)&hh0, *(uint32_t*)&hh1);
    __nv_bfloat162 ll0 = __halves2bfloat162(
        __float2bfloat16(v.x - __bfloat162float(h0)),
        __float2bfloat16(v.y - __bfloat162float(h1)));
    __nv_bfloat162 ll1 = __halves2bfloat162(
        __float2bfloat16(v.z - __bfloat162float(h2)),
        __float2bfloat16(v.w - __bfloat162float(h3)));
    *(uint2*)(g_xsl + (size_t)m * INNER + c) =
        make_uint2(*(uint32_t*)&ll0, *(uint32_t*)&ll1);
}

// ============================================================
// Chunked selective scan, NCHK=64/CLEN=32, batched x4.
// w = b*(NCHK*1024) + c*1024 + dpair
// ============================================================
__global__ __launch_bounds__(256) void scanA_kernel(const float* __restrict__ A_log)
{
    int w = blockIdx.x * 8 + (threadIdx.x >> 5);
    int lane = threadIdx.x & 31;
    int dpair = w & 1023;
    int c = (w >> 10) & (NCHK - 1);
    int b = w >> 16;
    int d = dpair * 2 + ((lane >> 4) & 1);
    int n = lane & 15;

    float a = -__expf(A_log[d * DST + n]);
    float h = 0.f, dts = 0.f;
    size_t m0 = (size_t)b * LSEQ + c * CLEN;
    for (int tt = 0; tt < CLEN; tt += 4) {
        size_t m = m0 + tt;
        float dt0 = g_dt[(m + 0) * INNER + d], dt1 = g_dt[(m + 1) * INNER + d];
        float dt2 = g_dt[(m + 2) * INNER + d], dt3 = g_dt[(m + 3) * INNER + d];
        float xv0 = g_xs[(m + 0) * INNER + d], xv1 = g_xs[(m + 1) * INNER + d];
        float xv2 = g_xs[(m + 2) * INNER + d], xv3 = g_xs[(m + 3) * INNER + d];
        float B0 = g_xdbl[(m + 0) * XD + DTR + n], B1 = g_xdbl[(m + 1) * XD + DTR + n];
        float B2 = g_xdbl[(m + 2) * XD + DTR + n], B3 = g_xdbl[(m + 3) * XD + DTR + n];
        h = fmaf(__expf(dt0 * a), h, dt0 * B0 * xv0);
        h = fmaf(__expf(dt1 * a), h, dt1 * B1 * xv1);
        h = fmaf(__expf(dt2 * a), h, dt2 * B2 * xv2);
        h = fmaf(__expf(dt3 * a), h, dt3 * B3 * xv3);
        dts += dt0 + dt1 + dt2 + dt3;
    }
    size_t slot = (size_t)(b * NCHK + c) * INNER + d;
    g_hc[slot * DST + n] = h;
    if (n == 0) g_dts[slot] = dts;
}

__global__ __launch_bounds__(256) void scanB_kernel(const float* __restrict__ A_log)
{
    int idx = blockIdx.x * 256 + threadIdx.x;       // 0..65535
    int n = idx & 15;
    int d = (idx >> 4) & (INNER - 1);
    int b = idx >> 15;
    float a = -__expf(A_log[d * DST + n]);
    float s = 0.f;
#pragma unroll
    for (int c = 0; c < NCHK; c++) {
        size_t slot = (size_t)(b * NCHK + c) * INNER + d;
        g_hi[slot * DST + n] = s;
        s = fmaf(__expf(a * g_dts[slot]), s, g_hc[slot * DST + n]);
    }
}

__global__ __launch_bounds__(256) void scanC_kernel(const float* __restrict__ A_log,
                                                    const float* __restrict__ D_par)
{
    int w = blockIdx.x * 8 + (threadIdx.x >> 5);
    int lane = threadIdx.x & 31;
    int dpair = w & 1023;
    int c = (w >> 10) & (NCHK - 1);
    int b = w >> 16;
    int d = dpair * 2 + ((lane >> 4) & 1);
    int n = lane & 15;

    float a = -__expf(A_log[d * DST + n]);
    float Dv = D_par[d];
    size_t slot = (size_t)(b * NCHK + c) * INNER + d;
    float h = g_hi[slot * DST + n];

    size_t m0 = (size_t)b * LSEQ + c * CLEN;
    for (int tt = 0; tt < CLEN; tt += 4) {
        size_t m = m0 + tt;
        float dt0 = g_dt[(m + 0) * INNER + d], dt1 = g_dt[(m + 1) * INNER + d];
        float dt2 = g_dt[(m + 2) * INNER + d], dt3 = g_dt[(m + 3) * INNER + d];
        float xv0 = g_xs[(m + 0) * INNER + d], xv1 = g_xs[(m + 1) * INNER + d];
        float xv2 = g_xs[(m + 2) * INNER + d], xv3 = g_xs[(m + 3) * INNER + d];
        float B0 = g_xdbl[(m + 0) * XD + DTR + n], B1 = g_xdbl[(m + 1) * XD + DTR + n];
        float B2 = g_xdbl[(m + 2) * XD + DTR + n], B3 = g_xdbl[(m + 3) * XD + DTR + n];
        float C0 = g_xdbl[(m + 0) * XD + DTR + DST + n], C1 = g_xdbl[(m + 1) * XD + DTR + DST + n];
        float C2 = g_xdbl[(m + 2) * XD + DTR + DST + n], C3 = g_xdbl[(m + 3) * XD + DTR + DST + n];
        float r0 = 0.f, r1 = 0.f, r2 = 0.f, r3 = 0.f;
        if (n == 0) {
            r0 = g_xr[(m + 0) * NIN + INNER + d]; r1 = g_xr[(m + 1) * NIN + INNER + d];
            r2 = g_xr[(m + 2) * NIN + INNER + d]; r3 = g_xr[(m + 3) * NIN + INNER + d];
        }
#pragma unroll
        for (int q = 0; q < 4; q++) {
            float dt = q == 0 ? dt0 : q == 1 ? dt1 : q == 2 ? dt2 : dt3;
            float xv = q == 0 ? xv0 : q == 1 ? xv1 : q == 2 ? xv2 : xv3;
            float Bn = q == 0 ? B0 : q == 1 ? B1 : q == 2 ? B2 : B3;
            float Cn = q == 0 ? C0 : q == 1 ? C1 : q == 2 ? C2 : C3;
            float rv = q == 0 ? r0 : q == 1 ? r1 : q == 2 ? r2 : r3;
            h = fmaf(__expf(dt * a), h, dt * Bn * xv);
            float pv = h * Cn;
            pv += __shfl_xor_sync(0xffffffffu, pv, 8);
            pv += __shfl_xor_sync(0xffffffffu, pv, 4);
            pv += __shfl_xor_sync(0xffffffffu, pv, 2);
            pv += __shfl_xor_sync(0xffffffffu, pv, 1);
            if (n == 0) {
                float silu_r = rv / (1.f + __expf(-rv));
                float v = (pv + xv * Dv) * silu_r;
                __nv_bfloat16 vh = __float2bfloat16(v);
                __nv_bfloat16 vl = __float2bfloat16(v - __bfloat162float(vh));
                g_yh[(m + q) * INNER + d] = vh;
                g_yl[(m + q) * INNER + d] = vl;
            }
        }
    }
}

// ============================================================
extern "C" void kernel_launch(void* const* d_in, const int* in_sizes, int n_in,
                              void* d_out, int out_size)
{
    const float* x      = (const float*)d_in[0];
    const float* W_in   = (const float*)d_in[1];
    const float* conv_w = (const float*)d_in[2];
    const float* conv_b = (const float*)d_in[3];
    const float* W_x    = (const float*)d_in[4];
    const float* W_dt   = (const float*)d_in[5];
    const float* b_dt   = (const float*)d_in[6];
    const float* A_log  = (const float*)d_in[7];
    const float* D_par  = (const float*)d_in[8];
    const float* W_out  = (const float*)d_in[9];
    float* out = (float*)d_out;

    float *xr_p, *xdp_p;
    __nv_bfloat16 *xh_p, *xl_p, *wih_p, *wil_p, *woh_p, *wol_p, *yh_p, *yl_p;
    __nv_bfloat16 *xsh_p, *xsl_p, *wxh_p, *wxl_p;
    cudaGetSymbolAddress((void**)&xr_p,   g_xr);
    cudaGetSymbolAddress((void**)&xdp_p,  g_xdp);
    cudaGetSymbolAddress((void**)&xh_p,   g_xh);
    cudaGetSymbolAddress((void**)&xl_p,   g_xl);
    cudaGetSymbolAddress((void**)&wih_p,  g_wih);
    cudaGetSymbolAddress((void**)&wil_p,  g_wil);
    cudaGetSymbolAddress((void**)&woh_p,  g_woh);
    cudaGetSymbolAddress((void**)&wol_p,  g_wol);
    cudaGetSymbolAddress((void**)&yh_p,   g_yh);
    cudaGetSymbolAddress((void**)&yl_p,   g_yl);
    cudaGetSymbolAddress((void**)&xsh_p,  g_xsh);
    cudaGetSymbolAddress((void**)&xsl_p,  g_xsl);
    cudaGetSymbolAddress((void**)&wxh_p,  g_wxh);
    cudaGetSymbolAddress((void**)&wxl_p,  g_wxl);

    const int SMEM_128 = 1024 + 2 * (2 * TC_A_BYTES + 2 * 128 * 128);   // 132096
    const int SMEM_256 = 1024 + 2 * (2 * TC_A_BYTES + 2 * 256 * 128);   // 197632
    cudaFuncSetAttribute(tc_gemm_split<128>,
                         cudaFuncAttributeMaxDynamicSharedMemorySize, SMEM_128);
    cudaFuncSetAttribute(tc_gemm_split<256>,
                         cudaFuncAttributeMaxDynamicSharedMemorySize, SMEM_256);
    cudaFuncSetAttribute(tc_dt_gemm,
                         cudaFuncAttributeMaxDynamicSharedMemorySize, TC_DT_SMEM);

    // 0) one fused bf16 split pass
    split_all_kernel<<<(SP_TOT + 255) / 256, 256>>>(
        (const float4*)x, (const float4*)W_in, (const float4*)W_out,
        (const float4*)W_x, (const float4*)W_dt);

    // 1) xr = x @ W_in^T  (BN=256)
    tc_gemm_split<256><<<dim3(NIN / 256, MROWS / TC_BM, 1), 256, SMEM_256>>>(
        xh_p, xl_p, wih_p, wil_p, xr_p, DMODEL, DMODEL, DMODEL, NIN, NIN, 0, 0);

    // 2) depthwise causal conv + silu (vectorized)
    conv_silu_kernel<<<(MROWS * INNER / 4 + 255) / 256, 256>>>(conv_w, conv_b);

    // 3) x_dbl split-K x4 (BN=128), then reduce
    tc_gemm_split<128><<<dim3(1, MROWS / TC_BM, KSLC), 256, SMEM_128>>>(
        xsh_p, xsl_p, wxh_p, wxl_p, xdp_p, INNER, INNER, INNER / KSLC, XD, XD,
        INNER / KSLC, (size_t)MROWS * XD);
    reduce_xdbl_kernel<<<(MROWS * XD + 255) / 256, 256>>>();

    // 4) dt = log(2 + exp(xdbl[:,:64] @ W_dt^T + b_dt))
    tc_dt_gemm<<<dim3(INNER / 128, MROWS / TC_BM), 256, TC_DT_SMEM>>>(b_dt);

    // 5) chunked selective scan (NCHK=64 -> 131072 warps for A/C)
    scanA_kernel<<<16384, 256>>>(A_log);
    scanB_kernel<<<256, 256>>>(A_log);
    scanC_kernel<<<16384, 256>>>(A_log, D_par);

    // 6) out = y @ W_out^T  (BN=256)
    tc_gemm_split<256><<<dim3(DMODEL / 256, MROWS / TC_BM, 1), 256, SMEM_256>>>(
        yh_p, yl_p, woh_p, wol_p, out, INNER, INNER, INNER, DMODEL, DMODEL, 0, 0);
}